// round 12
// baseline (speedup 1.0000x reference)
#include <cuda_runtime.h>

#define BATCH 16
#define SEQ   320
#define DM    192
#define DI    384
#define DS    16
#define DTR   12
#define NLAYER 24
#define NROWS (BATCH*SEQ)   // 5120
#define NCHUNK 8
#define CLEN  (SEQ/NCHUNK)  // 40

// ---------------- f32x2 packed helpers (Blackwell FFMA2 path) ----------------
__device__ __forceinline__ double ffma2(double a, double b, double c) {
    double d; asm("fma.rn.f32x2 %0,%1,%2,%3;" : "=d"(d) : "d"(a), "d"(b), "d"(c)); return d;
}
__device__ __forceinline__ double fmul2(double a, double b) {
    double d; asm("mul.rn.f32x2 %0,%1,%2;" : "=d"(d) : "d"(a), "d"(b)); return d;
}
__device__ __forceinline__ double pack2(float lo, float hi) {
    double d; asm("mov.b64 %0,{%1,%2};" : "=d"(d) : "f"(lo), "f"(hi)); return d;
}
__device__ __forceinline__ void unpack2(double d, float& lo, float& hi) {
    asm("mov.b64 {%0,%1},%2;" : "=f"(lo), "=f"(hi) : "d"(d));
}

// ---------------- scratch (no allocations allowed) ----------------
__device__ __align__(128) float g_res[NROWS*DM];
__device__ __align__(128) float g_hid[NROWS*DM];
__device__ __align__(128) float g_hn [NROWS*DM];
__device__ __align__(128) float g_xz [NROWS*2*DI];
__device__ __align__(128) float g_xc [NROWS*DI];
__device__ __align__(128) float g_dbl[NROWS*64];
__device__ __align__(128) float g_dt [NROWS*DI];
__device__ __align__(128) float g_y  [NROWS*DI];
__device__ __align__(128) float g_sp [BATCH*NCHUNK*DI*DS];
__device__ __align__(128) float g_sh [BATCH*NCHUNK*DI*DS];

// ---------------- patch embed (+pos) -> g_hid ----------------
__global__ __launch_bounds__(192) void patch_kernel(
    const float* __restrict__ x_img, const float* __restrict__ z_img,
    const float* __restrict__ pw, const float* __restrict__ pb,
    const float* __restrict__ pos_x, const float* __restrict__ pos_z)
{
    __shared__ float sp[8*768];
    __shared__ float ws[192*17];
    int b   = blockIdx.y;
    int l0  = blockIdx.x * 8;
    int tid = threadIdx.x;
    bool is_z = (l0 < 64);
    const float* img = is_z ? z_img : x_img;
    int imgW = is_z ? 128 : 256;
    int gw   = is_z ? 8 : 16;
    const float* base = img + (size_t)b*3*imgW*imgW;

    for (int tok = 0; tok < 8; tok++) {
        int t  = is_z ? (l0+tok) : (l0+tok-64);
        int ph = t / gw, pwc = t % gw;
        const float* pbase = base + (size_t)(ph*16)*imgW + pwc*16;
        #pragma unroll
        for (int q = 0; q < 4; q++) {
            int idx = tid + q*192;
            int c = idx >> 8, r = idx & 255;
            sp[tok*768 + idx] = pbase[(size_t)c*imgW*imgW + (r>>4)*imgW + (r&15)];
        }
    }
    float acc[8];
    #pragma unroll
    for (int t = 0; t < 8; t++) acc[t] = 0.f;

    for (int k0 = 0; k0 < 768; k0 += 16) {
        __syncthreads();
        #pragma unroll
        for (int q = 0; q < 16; q++) {
            int idx = tid + q*192;
            int o = idx >> 4, kk = idx & 15;
            ws[o*17 + kk] = pw[(size_t)o*768 + k0 + kk];
        }
        __syncthreads();
        #pragma unroll
        for (int kk = 0; kk < 16; kk++) {
            float wv = ws[tid*17 + kk];
            #pragma unroll
            for (int t = 0; t < 8; t++)
                acc[t] = fmaf(wv, sp[t*768 + k0 + kk], acc[t]);
        }
    }
    float bias = pb[tid];
    for (int tok = 0; tok < 8; tok++) {
        int l = l0 + tok;
        float pos = is_z ? pos_z[(size_t)l*DM + tid] : pos_x[(size_t)(l-64)*DM + tid];
        g_hid[((size_t)b*SEQ + l)*DM + tid] = acc[tok] + bias + pos;
    }
}

// ---------------- fused residual add + layernorm ----------------
__global__ __launch_bounds__(128) void addnorm_kernel(
    const float* __restrict__ w, const float* __restrict__ bb,
    float* __restrict__ extout, int mode)
{
    int row  = blockIdx.x*4 + (threadIdx.x >> 5);
    int lane = threadIdx.x & 31;
    float*       res = g_res + (size_t)row*DM;
    const float* hid = g_hid + (size_t)row*DM;
    float v[6];
    #pragma unroll
    for (int q = 0; q < 6; q++) {
        int i = lane + q*32;
        float r = (mode == 0) ? hid[i] : (res[i] + hid[i]);
        res[i] = r;
        v[q] = r;
    }
    float s = v[0]+v[1]+v[2]+v[3]+v[4]+v[5];
    #pragma unroll
    for (int off = 16; off; off >>= 1) s += __shfl_xor_sync(0xffffffffu, s, off);
    float mu = s * (1.f/192.f);
    float var = 0.f;
    #pragma unroll
    for (int q = 0; q < 6; q++) { float dd = v[q]-mu; var = fmaf(dd, dd, var); }
    #pragma unroll
    for (int off = 16; off; off >>= 1) var += __shfl_xor_sync(0xffffffffu, var, off);
    float inv = rsqrtf(var*(1.f/192.f) + 1e-5f);
    float* outp = (mode == 2) ? (extout + (size_t)row*DM) : (g_hn + (size_t)row*DM);
    #pragma unroll
    for (int q = 0; q < 6; q++) {
        int i = lane + q*32;
        outp[i] = (v[q]-mu)*inv*w[i] + bb[i];
    }
}

// ================ big GEMM: 128x128 tile, 8x8 microtile, f32x2, double-buffered ================
__global__ __launch_bounds__(256) void gemm128_kernel(
    const float* __restrict__ A, const float* __restrict__ W,
    float* __restrict__ C, int K, int N)
{
    __shared__ __align__(16) float As[2][16][136];
    __shared__ __align__(16) float Ws[2][16][136];
    int m0 = blockIdx.x * 128;
    int n0 = blockIdx.y * 128;
    int tid = threadIdx.x;
    int lr  = tid >> 2;
    int lc  = (tid & 3) << 2;
    int tx  = tid & 15;
    int ty  = tid >> 4;
    const float* Ap0 = A + (size_t)(m0 + lr)*K + lc;
    const float* Ap1 = A + (size_t)(m0 + 64 + lr)*K + lc;
    const float* Wp0 = W + (size_t)(n0 + lr)*K + lc;
    const float* Wp1 = W + (size_t)(n0 + 64 + lr)*K + lc;

    float4 a0 = *(const float4*)Ap0;
    float4 a1 = *(const float4*)Ap1;
    float4 w0 = *(const float4*)Wp0;
    float4 w1 = *(const float4*)Wp1;

    double acc2[8][4];
    #pragma unroll
    for (int i = 0; i < 8; i++)
        #pragma unroll
        for (int j = 0; j < 4; j++) acc2[i][j] = 0.0;

    int ktiles = K >> 4;
    int buf = 0;
    As[0][lc+0][lr]=a0.x; As[0][lc+1][lr]=a0.y; As[0][lc+2][lr]=a0.z; As[0][lc+3][lr]=a0.w;
    As[0][lc+0][64+lr]=a1.x; As[0][lc+1][64+lr]=a1.y; As[0][lc+2][64+lr]=a1.z; As[0][lc+3][64+lr]=a1.w;
    Ws[0][lc+0][lr]=w0.x; Ws[0][lc+1][lr]=w0.y; Ws[0][lc+2][lr]=w0.z; Ws[0][lc+3][lr]=w0.w;
    Ws[0][lc+0][64+lr]=w1.x; Ws[0][lc+1][64+lr]=w1.y; Ws[0][lc+2][64+lr]=w1.z; Ws[0][lc+3][64+lr]=w1.w;
    __syncthreads();

    for (int t = 1; t < ktiles; t++) {
        a0 = *(const float4*)(Ap0 + t*16);
        a1 = *(const float4*)(Ap1 + t*16);
        w0 = *(const float4*)(Wp0 + t*16);
        w1 = *(const float4*)(Wp1 + t*16);
        #pragma unroll
        for (int k = 0; k < 16; k++) {
            float4 aA = *(const float4*)&As[buf][k][ty<<3];
            float4 aB = *(const float4*)&As[buf][k][(ty<<3)+4];
            double2 bd0 = *(const double2*)&Ws[buf][k][tx<<3];
            double2 bd1 = *(const double2*)&Ws[buf][k][(tx<<3)+4];
            double am2[8];
            am2[0]=pack2(aA.x,aA.x); am2[1]=pack2(aA.y,aA.y);
            am2[2]=pack2(aA.z,aA.z); am2[3]=pack2(aA.w,aA.w);
            am2[4]=pack2(aB.x,aB.x); am2[5]=pack2(aB.y,aB.y);
            am2[6]=pack2(aB.z,aB.z); am2[7]=pack2(aB.w,aB.w);
            #pragma unroll
            for (int i = 0; i < 8; i++) {
                acc2[i][0] = ffma2(am2[i], bd0.x, acc2[i][0]);
                acc2[i][1] = ffma2(am2[i], bd0.y, acc2[i][1]);
                acc2[i][2] = ffma2(am2[i], bd1.x, acc2[i][2]);
                acc2[i][3] = ffma2(am2[i], bd1.y, acc2[i][3]);
            }
        }
        int ob = buf ^ 1;
        As[ob][lc+0][lr]=a0.x; As[ob][lc+1][lr]=a0.y; As[ob][lc+2][lr]=a0.z; As[ob][lc+3][lr]=a0.w;
        As[ob][lc+0][64+lr]=a1.x; As[ob][lc+1][64+lr]=a1.y; As[ob][lc+2][64+lr]=a1.z; As[ob][lc+3][64+lr]=a1.w;
        Ws[ob][lc+0][lr]=w0.x; Ws[ob][lc+1][lr]=w0.y; Ws[ob][lc+2][lr]=w0.z; Ws[ob][lc+3][lr]=w0.w;
        Ws[ob][lc+0][64+lr]=w1.x; Ws[ob][lc+1][64+lr]=w1.y; Ws[ob][lc+2][64+lr]=w1.z; Ws[ob][lc+3][64+lr]=w1.w;
        __syncthreads();
        buf = ob;
    }
    #pragma unroll
    for (int k = 0; k < 16; k++) {
        float4 aA = *(const float4*)&As[buf][k][ty<<3];
        float4 aB = *(const float4*)&As[buf][k][(ty<<3)+4];
        double2 bd0 = *(const double2*)&Ws[buf][k][tx<<3];
        double2 bd1 = *(const double2*)&Ws[buf][k][(tx<<3)+4];
        double am2[8];
        am2[0]=pack2(aA.x,aA.x); am2[1]=pack2(aA.y,aA.y);
        am2[2]=pack2(aA.z,aA.z); am2[3]=pack2(aA.w,aA.w);
        am2[4]=pack2(aB.x,aB.x); am2[5]=pack2(aB.y,aB.y);
        am2[6]=pack2(aB.z,aB.z); am2[7]=pack2(aB.w,aB.w);
        #pragma unroll
        for (int i = 0; i < 8; i++) {
            acc2[i][0] = ffma2(am2[i], bd0.x, acc2[i][0]);
            acc2[i][1] = ffma2(am2[i], bd0.y, acc2[i][1]);
            acc2[i][2] = ffma2(am2[i], bd1.x, acc2[i][2]);
            acc2[i][3] = ffma2(am2[i], bd1.y, acc2[i][3]);
        }
    }
    #pragma unroll
    for (int i = 0; i < 8; i++) {
        float* crow = C + (size_t)(m0 + (ty<<3) + i)*N + n0 + (tx<<3);
        *(double2*)crow       = make_double2(acc2[i][0], acc2[i][1]);
        *(double2*)(crow + 4) = make_double2(acc2[i][2], acc2[i][3]);
    }
}

// ================ out_proj GEMM: 128x64 tile, 8x4 microtile, f32x2, double-buffered ================
__global__ __launch_bounds__(256) void gemm_n64_kernel(
    const float* __restrict__ A, const float* __restrict__ W,
    float* __restrict__ C, int K, int N)
{
    __shared__ __align__(16) float As[2][16][136];
    __shared__ __align__(16) float Ws[2][16][72];
    int m0 = blockIdx.x * 128;
    int n0 = blockIdx.y * 64;
    int tid = threadIdx.x;
    int lr  = tid >> 2;
    int lc  = (tid & 3) << 2;
    int tx  = tid & 15;
    int ty  = tid >> 4;
    const float* Ap0 = A + (size_t)(m0 + lr)*K + lc;
    const float* Ap1 = A + (size_t)(m0 + 64 + lr)*K + lc;
    const float* Wp  = W + (size_t)(n0 + lr)*K + lc;

    float4 a0 = *(const float4*)Ap0;
    float4 a1 = *(const float4*)Ap1;
    float4 w0 = *(const float4*)Wp;

    double acc2[8][2];
    #pragma unroll
    for (int i = 0; i < 8; i++) { acc2[i][0] = 0.0; acc2[i][1] = 0.0; }

    int ktiles = K >> 4;
    int buf = 0;
    As[0][lc+0][lr]=a0.x; As[0][lc+1][lr]=a0.y; As[0][lc+2][lr]=a0.z; As[0][lc+3][lr]=a0.w;
    As[0][lc+0][64+lr]=a1.x; As[0][lc+1][64+lr]=a1.y; As[0][lc+2][64+lr]=a1.z; As[0][lc+3][64+lr]=a1.w;
    Ws[0][lc+0][lr]=w0.x; Ws[0][lc+1][lr]=w0.y; Ws[0][lc+2][lr]=w0.z; Ws[0][lc+3][lr]=w0.w;
    __syncthreads();

    for (int t = 1; t < ktiles; t++) {
        a0 = *(const float4*)(Ap0 + t*16);
        a1 = *(const float4*)(Ap1 + t*16);
        w0 = *(const float4*)(Wp  + t*16);
        #pragma unroll
        for (int k = 0; k < 16; k++) {
            float4 aA = *(const float4*)&As[buf][k][ty<<3];
            float4 aB = *(const float4*)&As[buf][k][(ty<<3)+4];
            double2 bd = *(const double2*)&Ws[buf][k][tx<<2];
            double am2[8];
            am2[0]=pack2(aA.x,aA.x); am2[1]=pack2(aA.y,aA.y);
            am2[2]=pack2(aA.z,aA.z); am2[3]=pack2(aA.w,aA.w);
            am2[4]=pack2(aB.x,aB.x); am2[5]=pack2(aB.y,aB.y);
            am2[6]=pack2(aB.z,aB.z); am2[7]=pack2(aB.w,aB.w);
            #pragma unroll
            for (int i = 0; i < 8; i++) {
                acc2[i][0] = ffma2(am2[i], bd.x, acc2[i][0]);
                acc2[i][1] = ffma2(am2[i], bd.y, acc2[i][1]);
            }
        }
        int ob = buf ^ 1;
        As[ob][lc+0][lr]=a0.x; As[ob][lc+1][lr]=a0.y; As[ob][lc+2][lr]=a0.z; As[ob][lc+3][lr]=a0.w;
        As[ob][lc+0][64+lr]=a1.x; As[ob][lc+1][64+lr]=a1.y; As[ob][lc+2][64+lr]=a1.z; As[ob][lc+3][64+lr]=a1.w;
        Ws[ob][lc+0][lr]=w0.x; Ws[ob][lc+1][lr]=w0.y; Ws[ob][lc+2][lr]=w0.z; Ws[ob][lc+3][lr]=w0.w;
        __syncthreads();
        buf = ob;
    }
    #pragma unroll
    for (int k = 0; k < 16; k++) {
        float4 aA = *(const float4*)&As[buf][k][ty<<3];
        float4 aB = *(const float4*)&As[buf][k][(ty<<3)+4];
        double2 bd = *(const double2*)&Ws[buf][k][tx<<2];
        double am2[8];
        am2[0]=pack2(aA.x,aA.x); am2[1]=pack2(aA.y,aA.y);
        am2[2]=pack2(aA.z,aA.z); am2[3]=pack2(aA.w,aA.w);
        am2[4]=pack2(aB.x,aB.x); am2[5]=pack2(aB.y,aB.y);
        am2[6]=pack2(aB.z,aB.z); am2[7]=pack2(aB.w,aB.w);
        #pragma unroll
        for (int i = 0; i < 8; i++) {
            acc2[i][0] = ffma2(am2[i], bd.x, acc2[i][0]);
            acc2[i][1] = ffma2(am2[i], bd.y, acc2[i][1]);
        }
    }
    #pragma unroll
    for (int i = 0; i < 8; i++) {
        float* crow = C + (size_t)(m0 + (ty<<3) + i)*N + n0 + (tx<<2);
        *(double2*)crow = make_double2(acc2[i][0], acc2[i][1]);
    }
}

// ======== fused conv+silu+x_proj: 64x64 tile, grid (80,1) ========
// Each block owns 64 unique rows. A-staging computes causal depthwise conv
// (k=4) + silu from g_xz on the fly, side-writes g_xc (for the scans), and
// feeds the GEMM from smem. C = dbl (ldc 64, N=44).
__global__ __launch_bounds__(256) void gemm_xconv_kernel(
    const float* __restrict__ W,
    const float* __restrict__ cw, const float* __restrict__ cb,
    float* __restrict__ C)
{
    const int N = 44, K = DI, ldc = 64;
    __shared__ __align__(16) float As[2][16][72];
    __shared__ __align__(16) float Ws[2][16][72];
    int m0 = blockIdx.x * 64;
    int tid = threadIdx.x;
    int tx = tid & 15, ty = tid >> 4;
    int lr = tid >> 2;
    int lk = (tid & 3) << 2;
    int row = m0 + lr;
    int l   = row % SEQ;
    const float* xzp = g_xz + (size_t)row*768;
    float*       xco = g_xc + (size_t)row*DI;
    bool wvalid = (lr < N);
    const float* Wptr = W + (size_t)(wvalid ? lr : 0)*K + lk;

    const float4 f4z = make_float4(0.f,0.f,0.f,0.f);

    // conv+silu of 4 channels d0..d0+3 at this row
    auto convq = [&](int d0) -> float4 {
        float4 x0  = *(const float4*)(xzp + d0);
        float4 xm1 = (l >= 1) ? *(const float4*)(xzp - 768  + d0) : f4z;
        float4 xm2 = (l >= 2) ? *(const float4*)(xzp - 1536 + d0) : f4z;
        float4 xm3 = (l >= 3) ? *(const float4*)(xzp - 2304 + d0) : f4z;
        float4 wa = *(const float4*)(cw + d0*4);
        float4 wb = *(const float4*)(cw + d0*4 + 4);
        float4 wc = *(const float4*)(cw + d0*4 + 8);
        float4 wd = *(const float4*)(cw + d0*4 + 12);
        float4 bv = *(const float4*)(cb + d0);
        float4 y;
        y.x = fmaf(wa.w,x0.x, fmaf(wa.z,xm1.x, fmaf(wa.y,xm2.x, fmaf(wa.x,xm3.x, bv.x))));
        y.y = fmaf(wb.w,x0.y, fmaf(wb.z,xm1.y, fmaf(wb.y,xm2.y, fmaf(wb.x,xm3.y, bv.y))));
        y.z = fmaf(wc.w,x0.z, fmaf(wc.z,xm1.z, fmaf(wc.y,xm2.z, fmaf(wc.x,xm3.z, bv.z))));
        y.w = fmaf(wd.w,x0.w, fmaf(wd.z,xm1.w, fmaf(wd.y,xm2.w, fmaf(wd.x,xm3.w, bv.w))));
        float4 v;
        v.x = __fdividef(y.x, 1.f + __expf(-y.x));
        v.y = __fdividef(y.y, 1.f + __expf(-y.y));
        v.z = __fdividef(y.z, 1.f + __expf(-y.z));
        v.w = __fdividef(y.w, 1.f + __expf(-y.w));
        return v;
    };

    float4 av = convq(lk);
    float4 wv = wvalid ? *(const float4*)Wptr : f4z;
    *(float4*)(xco + lk) = av;
    As[0][lk+0][lr]=av.x; As[0][lk+1][lr]=av.y; As[0][lk+2][lr]=av.z; As[0][lk+3][lr]=av.w;
    Ws[0][lk+0][lr]=wv.x; Ws[0][lk+1][lr]=wv.y; Ws[0][lk+2][lr]=wv.z; Ws[0][lk+3][lr]=wv.w;
    __syncthreads();

    double acc2[4][2];
    #pragma unroll
    for (int i = 0; i < 4; i++) { acc2[i][0] = 0.0; acc2[i][1] = 0.0; }

    int ktiles = K >> 4;   // 24
    int buf = 0;
    for (int t = 1; t < ktiles; t++) {
        int d0 = t*16 + lk;
        float4 av2 = convq(d0);
        float4 wv2 = wvalid ? *(const float4*)(Wptr + t*16) : f4z;
        *(float4*)(xco + d0) = av2;
        #pragma unroll
        for (int k = 0; k < 16; k++) {
            float4 a4 = *(const float4*)&As[buf][k][ty<<2];
            double2 bd = *(const double2*)&Ws[buf][k][tx<<2];
            double am2[4];
            am2[0]=pack2(a4.x,a4.x); am2[1]=pack2(a4.y,a4.y);
            am2[2]=pack2(a4.z,a4.z); am2[3]=pack2(a4.w,a4.w);
            #pragma unroll
            for (int i = 0; i < 4; i++) {
                acc2[i][0] = ffma2(am2[i], bd.x, acc2[i][0]);
                acc2[i][1] = ffma2(am2[i], bd.y, acc2[i][1]);
            }
        }
        int ob = buf ^ 1;
        As[ob][lk+0][lr]=av2.x; As[ob][lk+1][lr]=av2.y; As[ob][lk+2][lr]=av2.z; As[ob][lk+3][lr]=av2.w;
        Ws[ob][lk+0][lr]=wv2.x; Ws[ob][lk+1][lr]=wv2.y; Ws[ob][lk+2][lr]=wv2.z; Ws[ob][lk+3][lr]=wv2.w;
        __syncthreads();
        buf = ob;
    }
    #pragma unroll
    for (int k = 0; k < 16; k++) {
        float4 a4 = *(const float4*)&As[buf][k][ty<<2];
        double2 bd = *(const double2*)&Ws[buf][k][tx<<2];
        double am2[4];
        am2[0]=pack2(a4.x,a4.x); am2[1]=pack2(a4.y,a4.y);
        am2[2]=pack2(a4.z,a4.z); am2[3]=pack2(a4.w,a4.w);
        #pragma unroll
        for (int i = 0; i < 4; i++) {
            acc2[i][0] = ffma2(am2[i], bd.x, acc2[i][0]);
            acc2[i][1] = ffma2(am2[i], bd.y, acc2[i][1]);
        }
    }
    #pragma unroll
    for (int i = 0; i < 4; i++) {
        int crow_i = m0 + (ty<<2) + i;
        int c0  = tx<<2;
        float f0,f1,f2,f3;
        unpack2(acc2[i][0], f0, f1);
        unpack2(acc2[i][1], f2, f3);
        float* crow = C + (size_t)crow_i*ldc + c0;
        if (c0+0 < N) crow[0] = f0;
        if (c0+1 < N) crow[1] = f1;
        if (c0+2 < N) crow[2] = f2;
        if (c0+3 < N) crow[3] = f3;
    }
}

// ---------------- dt_proj + softplus ----------------
__global__ __launch_bounds__(256) void dt_kernel(
    const float* __restrict__ dtw, const float* __restrict__ dtb)
{
    int id = blockIdx.x*256 + threadIdx.x;
    if (id >= NROWS*DI) return;
    int d  = id % DI;
    int bl = id / DI;
    const float* row = g_dbl + (size_t)bl*64;
    const float* w   = dtw + d*DTR;
    float x = __ldg(dtb + d);
    #pragma unroll
    for (int r = 0; r < DTR; r++) x = fmaf(row[r], __ldg(w + r), x);
    g_dt[id] = (x > 20.f) ? x : log1pf(__expf(x));
}

// ============ chunked selective scan (NCHUNK=8, f32x2 state updates) ============
__global__ __launch_bounds__(64) void scanA_kernel(const float* __restrict__ A_log)
{
    __shared__ __align__(16) float sB[CLEN*DS];
    int c   = blockIdx.x;
    int d   = blockIdx.y*64 + threadIdx.x;
    int b   = blockIdx.z;
    int l0  = c*CLEN;
    for (int idx = threadIdx.x; idx < CLEN*DS; idx += 64) {
        int l = idx >> 4, n = idx & 15;
        sB[idx] = g_dbl[((size_t)b*SEQ + l0 + l)*64 + 12 + n];
    }
    __syncthreads();
    float Av[DS];
    bool fast = true;
    #pragma unroll
    for (int n = 0; n < DS; n++) {
        Av[n] = -__expf(A_log[(size_t)d*DS + n]);
        fast = fast && (fabsf(Av[n] + (float)(n+1)) < 1e-5f*(float)(n+1));
    }
    const float* dtp = g_dt + ((size_t)b*SEQ + l0)*DI + d;
    const float* xcp = g_xc + ((size_t)b*SEQ + l0)*DI + d;
    size_t base = (((size_t)b*NCHUNK + c)*DI + d)*DS;

    if (fast) {
        double P2[8], h2[8];
        #pragma unroll
        for (int k = 0; k < 8; k++) { P2[k] = pack2(1.f,1.f); h2[k] = 0.0; }
        for (int l = 0; l < CLEN; l++) {
            float dtv = dtp[(size_t)l*DI];
            float xv  = xcp[(size_t)l*DI];
            float dtx = dtv * xv;
            float r = __expf(-dtv);
            float rr = r*r;
            double dA2[8];
            dA2[0] = pack2(r, rr);
            double rr2 = pack2(rr, rr);
            #pragma unroll
            for (int k = 1; k < 8; k++) dA2[k] = fmul2(dA2[k-1], rr2);
            double dtx2 = pack2(dtx, dtx);
            const double* B2 = (const double*)(sB + l*DS);
            #pragma unroll
            for (int k = 0; k < 8; k++) {
                P2[k] = fmul2(P2[k], dA2[k]);
                h2[k] = ffma2(dA2[k], h2[k], fmul2(dtx2, B2[k]));
            }
        }
        #pragma unroll
        for (int k = 0; k < 8; k++) {
            *(double*)(g_sp + base + 2*k) = P2[k];
            *(double*)(g_sh + base + 2*k) = h2[k];
        }
    } else {
        float P[DS], H[DS];
        #pragma unroll
        for (int n = 0; n < DS; n++) { P[n] = 1.f; H[n] = 0.f; }
        for (int l = 0; l < CLEN; l++) {
            float dtv = dtp[(size_t)l*DI];
            float xv  = xcp[(size_t)l*DI];
            float dtx = dtv * xv;
            const float* Bl = sB + l*DS;
            #pragma unroll
            for (int n = 0; n < DS; n++) {
                float dA = __expf(dtv * Av[n]);
                P[n] *= dA;
                H[n]  = fmaf(dA, H[n], dtx * Bl[n]);
            }
        }
        #pragma unroll
        for (int n = 0; n < DS; n++) { g_sp[base+n] = P[n]; g_sh[base+n] = H[n]; }
    }
}

__global__ __launch_bounds__(64) void scanC_kernel(
    const float* __restrict__ A_log, const float* __restrict__ Dskip)
{
    __shared__ __align__(16) float sB[CLEN*DS];
    __shared__ __align__(16) float sC[CLEN*DS];
    int c   = blockIdx.x;
    int d   = blockIdx.y*64 + threadIdx.x;
    int b   = blockIdx.z;
    int l0  = c*CLEN;
    for (int idx = threadIdx.x; idx < CLEN*DS; idx += 64) {
        int l = idx >> 4, n = idx & 15;
        const float* row = g_dbl + ((size_t)b*SEQ + l0 + l)*64;
        sB[idx] = row[12 + n];
        sC[idx] = row[28 + n];
    }
    __syncthreads();
    float Av[DS];
    bool fast = true;
    #pragma unroll
    for (int n = 0; n < DS; n++) {
        Av[n] = -__expf(A_log[(size_t)d*DS + n]);
        fast = fast && (fabsf(Av[n] + (float)(n+1)) < 1e-5f*(float)(n+1));
    }
    float dsk = __ldg(Dskip + d);
    const float* dtp = g_dt + ((size_t)b*SEQ + l0)*DI + d;
    const float* xcp = g_xc + ((size_t)b*SEQ + l0)*DI + d;
    const float* zgp = g_xz + ((size_t)b*SEQ + l0)*768 + DI + d;
    float*       yp  = g_y  + ((size_t)b*SEQ + l0)*DI + d;

    if (fast) {
        double h2[8];
        #pragma unroll
        for (int k = 0; k < 8; k++) h2[k] = 0.0;
        for (int cc = 0; cc < c; cc++) {
            size_t base = (((size_t)b*NCHUNK + cc)*DI + d)*DS;
            #pragma unroll
            for (int k = 0; k < 8; k++) {
                double sp2 = *(const double*)(g_sp + base + 2*k);
                double sh2 = *(const double*)(g_sh + base + 2*k);
                h2[k] = ffma2(sp2, h2[k], sh2);
            }
        }
        for (int l = 0; l < CLEN; l++) {
            float dtv = dtp[(size_t)l*DI];
            float xv  = xcp[(size_t)l*DI];
            float zv  = zgp[(size_t)l*768];
            float dtx = dtv * xv;
            float r = __expf(-dtv);
            float rr = r*r;
            double dA2[8];
            dA2[0] = pack2(r, rr);
            double rr2 = pack2(rr, rr);
            #pragma unroll
            for (int k = 1; k < 8; k++) dA2[k] = fmul2(dA2[k-1], rr2);
            double dtx2 = pack2(dtx, dtx);
            const double* B2 = (const double*)(sB + l*DS);
            const double* C2 = (const double*)(sC + l*DS);
            double a2a = pack2(xv*dsk, 0.f);
            double a2b = 0.0;
            #pragma unroll
            for (int k = 0; k < 8; k++) {
                h2[k] = ffma2(dA2[k], h2[k], fmul2(dtx2, B2[k]));
                if (k < 4) a2a = ffma2(h2[k], C2[k], a2a);
                else       a2b = ffma2(h2[k], C2[k], a2b);
            }
            float s0,s1,s2,s3;
            unpack2(a2a, s0, s1);
            unpack2(a2b, s2, s3);
            float acc = (s0+s1) + (s2+s3);
            float sg = __fdividef(zv, 1.f + __expf(-zv));
            yp[(size_t)l*DI] = acc * sg;
        }
    } else {
        float h[DS];
        #pragma unroll
        for (int n = 0; n < DS; n++) h[n] = 0.f;
        for (int cc = 0; cc < c; cc++) {
            size_t base = (((size_t)b*NCHUNK + cc)*DI + d)*DS;
            #pragma unroll
            for (int n = 0; n < DS; n++)
                h[n] = fmaf(__ldg(g_sp + base + n), h[n], __ldg(g_sh + base + n));
        }
        for (int l = 0; l < CLEN; l++) {
            float dtv = dtp[(size_t)l*DI];
            float xv  = xcp[(size_t)l*DI];
            float zv  = zgp[(size_t)l*768];
            float dtx = dtv * xv;
            const float* Bl = sB + l*DS;
            const float* Cl = sC + l*DS;
            float a0 = xv*dsk, a1 = 0.f, a2 = 0.f, a3 = 0.f;
            #pragma unroll
            for (int n = 0; n < DS; n += 4) {
                float d0 = __expf(dtv*Av[n+0]), d1 = __expf(dtv*Av[n+1]);
                float d2 = __expf(dtv*Av[n+2]), d3 = __expf(dtv*Av[n+3]);
                h[n+0] = fmaf(d0, h[n+0], dtx*Bl[n+0]);
                h[n+1] = fmaf(d1, h[n+1], dtx*Bl[n+1]);
                h[n+2] = fmaf(d2, h[n+2], dtx*Bl[n+2]);
                h[n+3] = fmaf(d3, h[n+3], dtx*Bl[n+3]);
                a0 = fmaf(h[n+0], Cl[n+0], a0);
                a1 = fmaf(h[n+1], Cl[n+1], a1);
                a2 = fmaf(h[n+2], Cl[n+2], a2);
                a3 = fmaf(h[n+3], Cl[n+3], a3);
            }
            float acc = (a0+a1) + (a2+a3);
            float sg = __fdividef(zv, 1.f + __expf(-zv));
            yp[(size_t)l*DI] = acc * sg;
        }
    }
}

// ---------------- host ----------------
extern "C" void kernel_launch(void* const* d_in, const int* in_sizes, int n_in,
                              void* d_out, int out_size)
{
    const float* x_img   = (const float*)d_in[0];
    const float* z_img   = (const float*)d_in[1];
    const float* patch_w = (const float*)d_in[2];
    const float* patch_b = (const float*)d_in[3];
    const float* pos_x   = (const float*)d_in[4];
    const float* pos_z   = (const float*)d_in[5];
    const float* ln_w    = (const float*)d_in[6];
    const float* ln_b    = (const float*)d_in[7];
    const float* in_w    = (const float*)d_in[8];
    const float* conv_w  = (const float*)d_in[9];
    const float* conv_b  = (const float*)d_in[10];
    const float* xproj_w = (const float*)d_in[11];
    const float* dt_w    = (const float*)d_in[12];
    const float* dt_b    = (const float*)d_in[13];
    const float* A_log   = (const float*)d_in[14];
    const float* D_skip  = (const float*)d_in[15];
    const float* out_w   = (const float*)d_in[16];
    const float* fnorm_w = (const float*)d_in[17];
    const float* fnorm_b = (const float*)d_in[18];

    float *p_hn, *p_xz, *p_xc, *p_dbl, *p_y, *p_hid;
    cudaGetSymbolAddress((void**)&p_hn,  g_hn);
    cudaGetSymbolAddress((void**)&p_xz,  g_xz);
    cudaGetSymbolAddress((void**)&p_xc,  g_xc);
    cudaGetSymbolAddress((void**)&p_dbl, g_dbl);
    cudaGetSymbolAddress((void**)&p_y,   g_y);
    cudaGetSymbolAddress((void**)&p_hid, g_hid);

    patch_kernel<<<dim3(40,16), 192>>>(x_img, z_img, patch_w, patch_b, pos_x, pos_z);

    for (int ly = 0; ly < NLAYER; ly++) {
        addnorm_kernel<<<1280,128>>>(ln_w + (size_t)ly*DM, ln_b + (size_t)ly*DM,
                                     nullptr, ly == 0 ? 0 : 1);
        gemm128_kernel<<<dim3(40,6),256>>>(p_hn, in_w + (size_t)ly*768*DM, p_xz,
                                           DM, 2*DI);
        gemm_xconv_kernel<<<80,256>>>(xproj_w + (size_t)ly*44*DI,
                                      conv_w + (size_t)ly*DI*4,
                                      conv_b + (size_t)ly*DI, p_dbl);
        dt_kernel<<<7680,256>>>(dt_w + (size_t)ly*DI*DTR, dt_b + (size_t)ly*DI);
        scanA_kernel<<<dim3(NCHUNK,6,BATCH),64>>>(A_log + (size_t)ly*DI*DS);
        scanC_kernel<<<dim3(NCHUNK,6,BATCH),64>>>(A_log + (size_t)ly*DI*DS,
                                                  D_skip + (size_t)ly*DI);
        gemm_n64_kernel<<<dim3(40,3),256>>>(p_y, out_w + (size_t)ly*DM*DI, p_hid,
                                            DI, DM);
    }
    addnorm_kernel<<<1280,128>>>(fnorm_w, fnorm_b, (float*)d_out, 2);
}

// round 14
// speedup vs baseline: 1.1238x; 1.1238x over previous
#include <cuda_runtime.h>

#define BATCH 16
#define SEQ   320
#define DM    192
#define DI    384
#define DS    16
#define DTR   12
#define NLAYER 24
#define NROWS (BATCH*SEQ)   // 5120
#define NCHUNK 8
#define CLEN  (SEQ/NCHUNK)  // 40

// ---------------- f32x2 packed helpers (Blackwell FFMA2 path) ----------------
__device__ __forceinline__ double ffma2(double a, double b, double c) {
    double d; asm("fma.rn.f32x2 %0,%1,%2,%3;" : "=d"(d) : "d"(a), "d"(b), "d"(c)); return d;
}
__device__ __forceinline__ double fmul2(double a, double b) {
    double d; asm("mul.rn.f32x2 %0,%1,%2;" : "=d"(d) : "d"(a), "d"(b)); return d;
}
__device__ __forceinline__ double pack2(float lo, float hi) {
    double d; asm("mov.b64 %0,{%1,%2};" : "=d"(d) : "f"(lo), "f"(hi)); return d;
}
__device__ __forceinline__ void unpack2(double d, float& lo, float& hi) {
    asm("mov.b64 {%0,%1},%2;" : "=f"(lo), "=f"(hi) : "d"(d));
}

// ---------------- scratch (no allocations allowed) ----------------
__device__ __align__(128) float g_res[NROWS*DM];
__device__ __align__(128) float g_hid[NROWS*DM];
__device__ __align__(128) float g_hn [NROWS*DM];
__device__ __align__(128) float g_xz [NROWS*2*DI];
__device__ __align__(128) float g_xc [NROWS*DI];
__device__ __align__(128) float g_dbl[NROWS*64];
__device__ __align__(128) float g_y  [NROWS*DI];
__device__ __align__(128) float g_sp [BATCH*NCHUNK*DI*DS];
__device__ __align__(128) float g_sh [BATCH*NCHUNK*DI*DS];

// ---------------- patch embed (+pos) -> g_hid ----------------
__global__ __launch_bounds__(192) void patch_kernel(
    const float* __restrict__ x_img, const float* __restrict__ z_img,
    const float* __restrict__ pw, const float* __restrict__ pb,
    const float* __restrict__ pos_x, const float* __restrict__ pos_z)
{
    __shared__ float sp[8*768];
    __shared__ float ws[192*17];
    int b   = blockIdx.y;
    int l0  = blockIdx.x * 8;
    int tid = threadIdx.x;
    bool is_z = (l0 < 64);
    const float* img = is_z ? z_img : x_img;
    int imgW = is_z ? 128 : 256;
    int gw   = is_z ? 8 : 16;
    const float* base = img + (size_t)b*3*imgW*imgW;

    for (int tok = 0; tok < 8; tok++) {
        int t  = is_z ? (l0+tok) : (l0+tok-64);
        int ph = t / gw, pwc = t % gw;
        const float* pbase = base + (size_t)(ph*16)*imgW + pwc*16;
        #pragma unroll
        for (int q = 0; q < 4; q++) {
            int idx = tid + q*192;
            int c = idx >> 8, r = idx & 255;
            sp[tok*768 + idx] = pbase[(size_t)c*imgW*imgW + (r>>4)*imgW + (r&15)];
        }
    }
    float acc[8];
    #pragma unroll
    for (int t = 0; t < 8; t++) acc[t] = 0.f;

    for (int k0 = 0; k0 < 768; k0 += 16) {
        __syncthreads();
        #pragma unroll
        for (int q = 0; q < 16; q++) {
            int idx = tid + q*192;
            int o = idx >> 4, kk = idx & 15;
            ws[o*17 + kk] = pw[(size_t)o*768 + k0 + kk];
        }
        __syncthreads();
        #pragma unroll
        for (int kk = 0; kk < 16; kk++) {
            float wv = ws[tid*17 + kk];
            #pragma unroll
            for (int t = 0; t < 8; t++)
                acc[t] = fmaf(wv, sp[t*768 + k0 + kk], acc[t]);
        }
    }
    float bias = pb[tid];
    for (int tok = 0; tok < 8; tok++) {
        int l = l0 + tok;
        float pos = is_z ? pos_z[(size_t)l*DM + tid] : pos_x[(size_t)(l-64)*DM + tid];
        g_hid[((size_t)b*SEQ + l)*DM + tid] = acc[tok] + bias + pos;
    }
}

// ---------------- fused residual add + layernorm ----------------
__global__ __launch_bounds__(128) void addnorm_kernel(
    const float* __restrict__ w, const float* __restrict__ bb,
    float* __restrict__ extout, int mode)
{
    int row  = blockIdx.x*4 + (threadIdx.x >> 5);
    int lane = threadIdx.x & 31;
    float*       res = g_res + (size_t)row*DM;
    const float* hid = g_hid + (size_t)row*DM;
    float v[6];
    #pragma unroll
    for (int q = 0; q < 6; q++) {
        int i = lane + q*32;
        float r = (mode == 0) ? hid[i] : (res[i] + hid[i]);
        res[i] = r;
        v[q] = r;
    }
    float s = v[0]+v[1]+v[2]+v[3]+v[4]+v[5];
    #pragma unroll
    for (int off = 16; off; off >>= 1) s += __shfl_xor_sync(0xffffffffu, s, off);
    float mu = s * (1.f/192.f);
    float var = 0.f;
    #pragma unroll
    for (int q = 0; q < 6; q++) { float dd = v[q]-mu; var = fmaf(dd, dd, var); }
    #pragma unroll
    for (int off = 16; off; off >>= 1) var += __shfl_xor_sync(0xffffffffu, var, off);
    float inv = rsqrtf(var*(1.f/192.f) + 1e-5f);
    float* outp = (mode == 2) ? (extout + (size_t)row*DM) : (g_hn + (size_t)row*DM);
    #pragma unroll
    for (int q = 0; q < 6; q++) {
        int i = lane + q*32;
        outp[i] = (v[q]-mu)*inv*w[i] + bb[i];
    }
}

// ================ big GEMM: 128x128 tile, 8x8 microtile, f32x2, double-buffered ================
__global__ __launch_bounds__(256) void gemm128_kernel(
    const float* __restrict__ A, const float* __restrict__ W,
    float* __restrict__ C, int K, int N)
{
    __shared__ __align__(16) float As[2][16][136];
    __shared__ __align__(16) float Ws[2][16][136];
    int m0 = blockIdx.x * 128;
    int n0 = blockIdx.y * 128;
    int tid = threadIdx.x;
    int lr  = tid >> 2;
    int lc  = (tid & 3) << 2;
    int tx  = tid & 15;
    int ty  = tid >> 4;
    const float* Ap0 = A + (size_t)(m0 + lr)*K + lc;
    const float* Ap1 = A + (size_t)(m0 + 64 + lr)*K + lc;
    const float* Wp0 = W + (size_t)(n0 + lr)*K + lc;
    const float* Wp1 = W + (size_t)(n0 + 64 + lr)*K + lc;

    float4 a0 = *(const float4*)Ap0;
    float4 a1 = *(const float4*)Ap1;
    float4 w0 = *(const float4*)Wp0;
    float4 w1 = *(const float4*)Wp1;

    double acc2[8][4];
    #pragma unroll
    for (int i = 0; i < 8; i++)
        #pragma unroll
        for (int j = 0; j < 4; j++) acc2[i][j] = 0.0;

    int ktiles = K >> 4;
    int buf = 0;
    As[0][lc+0][lr]=a0.x; As[0][lc+1][lr]=a0.y; As[0][lc+2][lr]=a0.z; As[0][lc+3][lr]=a0.w;
    As[0][lc+0][64+lr]=a1.x; As[0][lc+1][64+lr]=a1.y; As[0][lc+2][64+lr]=a1.z; As[0][lc+3][64+lr]=a1.w;
    Ws[0][lc+0][lr]=w0.x; Ws[0][lc+1][lr]=w0.y; Ws[0][lc+2][lr]=w0.z; Ws[0][lc+3][lr]=w0.w;
    Ws[0][lc+0][64+lr]=w1.x; Ws[0][lc+1][64+lr]=w1.y; Ws[0][lc+2][64+lr]=w1.z; Ws[0][lc+3][64+lr]=w1.w;
    __syncthreads();

    for (int t = 1; t < ktiles; t++) {
        a0 = *(const float4*)(Ap0 + t*16);
        a1 = *(const float4*)(Ap1 + t*16);
        w0 = *(const float4*)(Wp0 + t*16);
        w1 = *(const float4*)(Wp1 + t*16);
        #pragma unroll
        for (int k = 0; k < 16; k++) {
            float4 aA = *(const float4*)&As[buf][k][ty<<3];
            float4 aB = *(const float4*)&As[buf][k][(ty<<3)+4];
            double2 bd0 = *(const double2*)&Ws[buf][k][tx<<3];
            double2 bd1 = *(const double2*)&Ws[buf][k][(tx<<3)+4];
            double am2[8];
            am2[0]=pack2(aA.x,aA.x); am2[1]=pack2(aA.y,aA.y);
            am2[2]=pack2(aA.z,aA.z); am2[3]=pack2(aA.w,aA.w);
            am2[4]=pack2(aB.x,aB.x); am2[5]=pack2(aB.y,aB.y);
            am2[6]=pack2(aB.z,aB.z); am2[7]=pack2(aB.w,aB.w);
            #pragma unroll
            for (int i = 0; i < 8; i++) {
                acc2[i][0] = ffma2(am2[i], bd0.x, acc2[i][0]);
                acc2[i][1] = ffma2(am2[i], bd0.y, acc2[i][1]);
                acc2[i][2] = ffma2(am2[i], bd1.x, acc2[i][2]);
                acc2[i][3] = ffma2(am2[i], bd1.y, acc2[i][3]);
            }
        }
        int ob = buf ^ 1;
        As[ob][lc+0][lr]=a0.x; As[ob][lc+1][lr]=a0.y; As[ob][lc+2][lr]=a0.z; As[ob][lc+3][lr]=a0.w;
        As[ob][lc+0][64+lr]=a1.x; As[ob][lc+1][64+lr]=a1.y; As[ob][lc+2][64+lr]=a1.z; As[ob][lc+3][64+lr]=a1.w;
        Ws[ob][lc+0][lr]=w0.x; Ws[ob][lc+1][lr]=w0.y; Ws[ob][lc+2][lr]=w0.z; Ws[ob][lc+3][lr]=w0.w;
        Ws[ob][lc+0][64+lr]=w1.x; Ws[ob][lc+1][64+lr]=w1.y; Ws[ob][lc+2][64+lr]=w1.z; Ws[ob][lc+3][64+lr]=w1.w;
        __syncthreads();
        buf = ob;
    }
    #pragma unroll
    for (int k = 0; k < 16; k++) {
        float4 aA = *(const float4*)&As[buf][k][ty<<3];
        float4 aB = *(const float4*)&As[buf][k][(ty<<3)+4];
        double2 bd0 = *(const double2*)&Ws[buf][k][tx<<3];
        double2 bd1 = *(const double2*)&Ws[buf][k][(tx<<3)+4];
        double am2[8];
        am2[0]=pack2(aA.x,aA.x); am2[1]=pack2(aA.y,aA.y);
        am2[2]=pack2(aA.z,aA.z); am2[3]=pack2(aA.w,aA.w);
        am2[4]=pack2(aB.x,aB.x); am2[5]=pack2(aB.y,aB.y);
        am2[6]=pack2(aB.z,aB.z); am2[7]=pack2(aB.w,aB.w);
        #pragma unroll
        for (int i = 0; i < 8; i++) {
            acc2[i][0] = ffma2(am2[i], bd0.x, acc2[i][0]);
            acc2[i][1] = ffma2(am2[i], bd0.y, acc2[i][1]);
            acc2[i][2] = ffma2(am2[i], bd1.x, acc2[i][2]);
            acc2[i][3] = ffma2(am2[i], bd1.y, acc2[i][3]);
        }
    }
    #pragma unroll
    for (int i = 0; i < 8; i++) {
        float* crow = C + (size_t)(m0 + (ty<<3) + i)*N + n0 + (tx<<3);
        *(double2*)crow       = make_double2(acc2[i][0], acc2[i][1]);
        *(double2*)(crow + 4) = make_double2(acc2[i][2], acc2[i][3]);
    }
}

// ================ out_proj GEMM: 128x64 tile, 8x4 microtile, f32x2, double-buffered ================
__global__ __launch_bounds__(256) void gemm_n64_kernel(
    const float* __restrict__ A, const float* __restrict__ W,
    float* __restrict__ C, int K, int N)
{
    __shared__ __align__(16) float As[2][16][136];
    __shared__ __align__(16) float Ws[2][16][72];
    int m0 = blockIdx.x * 128;
    int n0 = blockIdx.y * 64;
    int tid = threadIdx.x;
    int lr  = tid >> 2;
    int lc  = (tid & 3) << 2;
    int tx  = tid & 15;
    int ty  = tid >> 4;
    const float* Ap0 = A + (size_t)(m0 + lr)*K + lc;
    const float* Ap1 = A + (size_t)(m0 + 64 + lr)*K + lc;
    const float* Wp  = W + (size_t)(n0 + lr)*K + lc;

    float4 a0 = *(const float4*)Ap0;
    float4 a1 = *(const float4*)Ap1;
    float4 w0 = *(const float4*)Wp;

    double acc2[8][2];
    #pragma unroll
    for (int i = 0; i < 8; i++) { acc2[i][0] = 0.0; acc2[i][1] = 0.0; }

    int ktiles = K >> 4;
    int buf = 0;
    As[0][lc+0][lr]=a0.x; As[0][lc+1][lr]=a0.y; As[0][lc+2][lr]=a0.z; As[0][lc+3][lr]=a0.w;
    As[0][lc+0][64+lr]=a1.x; As[0][lc+1][64+lr]=a1.y; As[0][lc+2][64+lr]=a1.z; As[0][lc+3][64+lr]=a1.w;
    Ws[0][lc+0][lr]=w0.x; Ws[0][lc+1][lr]=w0.y; Ws[0][lc+2][lr]=w0.z; Ws[0][lc+3][lr]=w0.w;
    __syncthreads();

    for (int t = 1; t < ktiles; t++) {
        a0 = *(const float4*)(Ap0 + t*16);
        a1 = *(const float4*)(Ap1 + t*16);
        w0 = *(const float4*)(Wp  + t*16);
        #pragma unroll
        for (int k = 0; k < 16; k++) {
            float4 aA = *(const float4*)&As[buf][k][ty<<3];
            float4 aB = *(const float4*)&As[buf][k][(ty<<3)+4];
            double2 bd = *(const double2*)&Ws[buf][k][tx<<2];
            double am2[8];
            am2[0]=pack2(aA.x,aA.x); am2[1]=pack2(aA.y,aA.y);
            am2[2]=pack2(aA.z,aA.z); am2[3]=pack2(aA.w,aA.w);
            am2[4]=pack2(aB.x,aB.x); am2[5]=pack2(aB.y,aB.y);
            am2[6]=pack2(aB.z,aB.z); am2[7]=pack2(aB.w,aB.w);
            #pragma unroll
            for (int i = 0; i < 8; i++) {
                acc2[i][0] = ffma2(am2[i], bd.x, acc2[i][0]);
                acc2[i][1] = ffma2(am2[i], bd.y, acc2[i][1]);
            }
        }
        int ob = buf ^ 1;
        As[ob][lc+0][lr]=a0.x; As[ob][lc+1][lr]=a0.y; As[ob][lc+2][lr]=a0.z; As[ob][lc+3][lr]=a0.w;
        As[ob][lc+0][64+lr]=a1.x; As[ob][lc+1][64+lr]=a1.y; As[ob][lc+2][64+lr]=a1.z; As[ob][lc+3][64+lr]=a1.w;
        Ws[ob][lc+0][lr]=w0.x; Ws[ob][lc+1][lr]=w0.y; Ws[ob][lc+2][lr]=w0.z; Ws[ob][lc+3][lr]=w0.w;
        __syncthreads();
        buf = ob;
    }
    #pragma unroll
    for (int k = 0; k < 16; k++) {
        float4 aA = *(const float4*)&As[buf][k][ty<<3];
        float4 aB = *(const float4*)&As[buf][k][(ty<<3)+4];
        double2 bd = *(const double2*)&Ws[buf][k][tx<<2];
        double am2[8];
        am2[0]=pack2(aA.x,aA.x); am2[1]=pack2(aA.y,aA.y);
        am2[2]=pack2(aA.z,aA.z); am2[3]=pack2(aA.w,aA.w);
        am2[4]=pack2(aB.x,aB.x); am2[5]=pack2(aB.y,aB.y);
        am2[6]=pack2(aB.z,aB.z); am2[7]=pack2(aB.w,aB.w);
        #pragma unroll
        for (int i = 0; i < 8; i++) {
            acc2[i][0] = ffma2(am2[i], bd.x, acc2[i][0]);
            acc2[i][1] = ffma2(am2[i], bd.y, acc2[i][1]);
        }
    }
    #pragma unroll
    for (int i = 0; i < 8; i++) {
        float* crow = C + (size_t)(m0 + (ty<<3) + i)*N + n0 + (tx<<2);
        *(double2*)crow = make_double2(acc2[i][0], acc2[i][1]);
    }
}

// ---------------- x_proj GEMM: 64x64 tile, f32x2, double-buffered ----------------
__global__ __launch_bounds__(256) void gemm_kernel(
    const float* __restrict__ A, const float* __restrict__ W,
    float* __restrict__ C, int M, int N, int K, int ldc)
{
    __shared__ __align__(16) float As[2][16][72];
    __shared__ __align__(16) float Ws[2][16][72];
    int m0 = blockIdx.x * 64;
    int n0 = blockIdx.y * 64;
    int tid = threadIdx.x;
    int tx = tid & 15, ty = tid >> 4;
    int lr = tid >> 2;
    int lk = (tid & 3) << 2;
    const float* Aptr = A + (size_t)(m0+lr)*K + lk;
    bool wvalid = (n0 + lr < N);
    const float* Wptr = W + (size_t)(wvalid ? (n0+lr) : 0)*K + lk;

    float4 av = *(const float4*)Aptr;
    float4 wv = wvalid ? *(const float4*)Wptr : make_float4(0.f,0.f,0.f,0.f);
    As[0][lk+0][lr]=av.x; As[0][lk+1][lr]=av.y; As[0][lk+2][lr]=av.z; As[0][lk+3][lr]=av.w;
    Ws[0][lk+0][lr]=wv.x; Ws[0][lk+1][lr]=wv.y; Ws[0][lk+2][lr]=wv.z; Ws[0][lk+3][lr]=wv.w;
    __syncthreads();

    double acc2[4][2];
    #pragma unroll
    for (int i = 0; i < 4; i++) { acc2[i][0] = 0.0; acc2[i][1] = 0.0; }

    int ktiles = K >> 4;
    int buf = 0;
    for (int t = 1; t < ktiles; t++) {
        float4 av2 = *(const float4*)(Aptr + t*16);
        float4 wv2 = wvalid ? *(const float4*)(Wptr + t*16) : make_float4(0.f,0.f,0.f,0.f);
        #pragma unroll
        for (int k = 0; k < 16; k++) {
            float4 a4 = *(const float4*)&As[buf][k][ty<<2];
            double2 bd = *(const double2*)&Ws[buf][k][tx<<2];
            double am2[4];
            am2[0]=pack2(a4.x,a4.x); am2[1]=pack2(a4.y,a4.y);
            am2[2]=pack2(a4.z,a4.z); am2[3]=pack2(a4.w,a4.w);
            #pragma unroll
            for (int i = 0; i < 4; i++) {
                acc2[i][0] = ffma2(am2[i], bd.x, acc2[i][0]);
                acc2[i][1] = ffma2(am2[i], bd.y, acc2[i][1]);
            }
        }
        int ob = buf ^ 1;
        As[ob][lk+0][lr]=av2.x; As[ob][lk+1][lr]=av2.y; As[ob][lk+2][lr]=av2.z; As[ob][lk+3][lr]=av2.w;
        Ws[ob][lk+0][lr]=wv2.x; Ws[ob][lk+1][lr]=wv2.y; Ws[ob][lk+2][lr]=wv2.z; Ws[ob][lk+3][lr]=wv2.w;
        __syncthreads();
        buf = ob;
    }
    #pragma unroll
    for (int k = 0; k < 16; k++) {
        float4 a4 = *(const float4*)&As[buf][k][ty<<2];
        double2 bd = *(const double2*)&Ws[buf][k][tx<<2];
        double am2[4];
        am2[0]=pack2(a4.x,a4.x); am2[1]=pack2(a4.y,a4.y);
        am2[2]=pack2(a4.z,a4.z); am2[3]=pack2(a4.w,a4.w);
        #pragma unroll
        for (int i = 0; i < 4; i++) {
            acc2[i][0] = ffma2(am2[i], bd.x, acc2[i][0]);
            acc2[i][1] = ffma2(am2[i], bd.y, acc2[i][1]);
        }
    }
    #pragma unroll
    for (int i = 0; i < 4; i++) {
        int row = m0 + (ty<<2) + i;
        int c0  = n0 + (tx<<2);
        float f0,f1,f2,f3;
        unpack2(acc2[i][0], f0, f1);
        unpack2(acc2[i][1], f2, f3);
        float* crow = C + (size_t)row*ldc + c0;
        if (c0+0 < N) crow[0] = f0;
        if (c0+1 < N) crow[1] = f1;
        if (c0+2 < N) crow[2] = f2;
        if (c0+3 < N) crow[3] = f3;
    }
}

// ---------------- causal depthwise conv (k=4) + silu, 4 timesteps/thread ----------------
__global__ __launch_bounds__(256) void conv_silu_kernel(
    const float* __restrict__ cw, const float* __restrict__ cb)
{
    int id = blockIdx.x*256 + threadIdx.x;
    int d  = id % DI;
    int t  = id / DI;
    int lq = t % (SEQ/4);
    int b  = t / (SEQ/4);
    int l0 = lq*4;
    const float* xp = g_xz + ((size_t)b*SEQ + l0)*768 + d;
    float x0 = xp[0], x1 = xp[768], x2 = xp[2*768], x3 = xp[3*768];
    float xm1 = 0.f, xm2 = 0.f, xm3 = 0.f;
    if (l0) { xm1 = xp[-768]; xm2 = xp[-2*768]; xm3 = xp[-3*768]; }
    float w0 = __ldg(cw + d*4 + 0), w1 = __ldg(cw + d*4 + 1);
    float w2 = __ldg(cw + d*4 + 2), w3 = __ldg(cw + d*4 + 3);
    float bv = __ldg(cb + d);
    float y0 = fmaf(w3,x0, fmaf(w2,xm1, fmaf(w1,xm2, fmaf(w0,xm3, bv))));
    float y1 = fmaf(w3,x1, fmaf(w2,x0,  fmaf(w1,xm1, fmaf(w0,xm2, bv))));
    float y2 = fmaf(w3,x2, fmaf(w2,x1,  fmaf(w1,x0,  fmaf(w0,xm1, bv))));
    float y3 = fmaf(w3,x3, fmaf(w2,x2,  fmaf(w1,x1,  fmaf(w0,x0,  bv))));
    float* yo = g_xc + ((size_t)b*SEQ + l0)*DI + d;
    yo[0]    = __fdividef(y0, 1.f + __expf(-y0));
    yo[DI]   = __fdividef(y1, 1.f + __expf(-y1));
    yo[2*DI] = __fdividef(y2, 1.f + __expf(-y2));
    yo[3*DI] = __fdividef(y3, 1.f + __expf(-y3));
}

// ============ chunked selective scan (NCHUNK=8, f32x2, fused dt_proj+softplus) ============
__global__ __launch_bounds__(64) void scanA_kernel(
    const float* __restrict__ A_log,
    const float* __restrict__ dtw, const float* __restrict__ dtb)
{
    __shared__ __align__(16) float sB[CLEN*DS];
    __shared__ __align__(16) float sdt[CLEN*DTR];
    int c   = blockIdx.x;
    int d   = blockIdx.y*64 + threadIdx.x;
    int b   = blockIdx.z;
    int l0  = c*CLEN;
    for (int idx = threadIdx.x; idx < CLEN*DS; idx += 64) {
        int l = idx >> 4, n = idx & 15;
        sB[idx] = g_dbl[((size_t)b*SEQ + l0 + l)*64 + 12 + n];
    }
    for (int idx = threadIdx.x; idx < CLEN*DTR; idx += 64) {
        int l = idx / DTR, r = idx - l*DTR;
        sdt[idx] = g_dbl[((size_t)b*SEQ + l0 + l)*64 + r];
    }
    __syncthreads();
    float Av[DS];
    bool fast = true;
    #pragma unroll
    for (int n = 0; n < DS; n++) {
        Av[n] = -__expf(A_log[(size_t)d*DS + n]);
        fast = fast && (fabsf(Av[n] + (float)(n+1)) < 1e-5f*(float)(n+1));
    }
    float wdt[DTR];
    #pragma unroll
    for (int r = 0; r < DTR; r++) wdt[r] = __ldg(dtw + (size_t)d*DTR + r);
    float bdt = __ldg(dtb + d);

    const float* xcp = g_xc + ((size_t)b*SEQ + l0)*DI + d;
    size_t base = (((size_t)b*NCHUNK + c)*DI + d)*DS;

    if (fast) {
        double P2[8], h2[8];
        #pragma unroll
        for (int k = 0; k < 8; k++) { P2[k] = pack2(1.f,1.f); h2[k] = 0.0; }
        for (int l = 0; l < CLEN; l++) {
            float x = bdt;
            #pragma unroll
            for (int r = 0; r < DTR; r++) x = fmaf(sdt[l*DTR+r], wdt[r], x);
            float dtv = (x > 20.f) ? x : log1pf(__expf(x));
            float xv  = xcp[(size_t)l*DI];
            float dtx = dtv * xv;
            float rv = __expf(-dtv);
            float rr = rv*rv;
            double dA2[8];
            dA2[0] = pack2(rv, rr);
            double rr2 = pack2(rr, rr);
            #pragma unroll
            for (int k = 1; k < 8; k++) dA2[k] = fmul2(dA2[k-1], rr2);
            double dtx2 = pack2(dtx, dtx);
            const double* B2 = (const double*)(sB + l*DS);
            #pragma unroll
            for (int k = 0; k < 8; k++) {
                P2[k] = fmul2(P2[k], dA2[k]);
                h2[k] = ffma2(dA2[k], h2[k], fmul2(dtx2, B2[k]));
            }
        }
        #pragma unroll
        for (int k = 0; k < 8; k++) {
            *(double*)(g_sp + base + 2*k) = P2[k];
            *(double*)(g_sh + base + 2*k) = h2[k];
        }
    } else {
        float P[DS], H[DS];
        #pragma unroll
        for (int n = 0; n < DS; n++) { P[n] = 1.f; H[n] = 0.f; }
        for (int l = 0; l < CLEN; l++) {
            float x = bdt;
            #pragma unroll
            for (int r = 0; r < DTR; r++) x = fmaf(sdt[l*DTR+r], wdt[r], x);
            float dtv = (x > 20.f) ? x : log1pf(__expf(x));
            float xv  = xcp[(size_t)l*DI];
            float dtx = dtv * xv;
            const float* Bl = sB + l*DS;
            #pragma unroll
            for (int n = 0; n < DS; n++) {
                float dA = __expf(dtv * Av[n]);
                P[n] *= dA;
                H[n]  = fmaf(dA, H[n], dtx * Bl[n]);
            }
        }
        #pragma unroll
        for (int n = 0; n < DS; n++) { g_sp[base+n] = P[n]; g_sh[base+n] = H[n]; }
    }
}

__global__ __launch_bounds__(64) void scanC_kernel(
    const float* __restrict__ A_log, const float* __restrict__ Dskip,
    const float* __restrict__ dtw, const float* __restrict__ dtb)
{
    __shared__ __align__(16) float sB[CLEN*DS];
    __shared__ __align__(16) float sC[CLEN*DS];
    __shared__ __align__(16) float sdt[CLEN*DTR];
    int c   = blockIdx.x;
    int d   = blockIdx.y*64 + threadIdx.x;
    int b   = blockIdx.z;
    int l0  = c*CLEN;
    for (int idx = threadIdx.x; idx < CLEN*DS; idx += 64) {
        int l = idx >> 4, n = idx & 15;
        const float* row = g_dbl + ((size_t)b*SEQ + l0 + l)*64;
        sB[idx] = row[12 + n];
        sC[idx] = row[28 + n];
    }
    for (int idx = threadIdx.x; idx < CLEN*DTR; idx += 64) {
        int l = idx / DTR, r = idx - l*DTR;
        sdt[idx] = g_dbl[((size_t)b*SEQ + l0 + l)*64 + r];
    }
    __syncthreads();
    float Av[DS];
    bool fast = true;
    #pragma unroll
    for (int n = 0; n < DS; n++) {
        Av[n] = -__expf(A_log[(size_t)d*DS + n]);
        fast = fast && (fabsf(Av[n] + (float)(n+1)) < 1e-5f*(float)(n+1));
    }
    float wdt[DTR];
    #pragma unroll
    for (int r = 0; r < DTR; r++) wdt[r] = __ldg(dtw + (size_t)d*DTR + r);
    float bdt = __ldg(dtb + d);
    float dsk = __ldg(Dskip + d);

    const float* xcp = g_xc + ((size_t)b*SEQ + l0)*DI + d;
    const float* zgp = g_xz + ((size_t)b*SEQ + l0)*768 + DI + d;
    float*       yp  = g_y  + ((size_t)b*SEQ + l0)*DI + d;

    if (fast) {
        double h2[8];
        #pragma unroll
        for (int k = 0; k < 8; k++) h2[k] = 0.0;
        for (int cc = 0; cc < c; cc++) {
            size_t base = (((size_t)b*NCHUNK + cc)*DI + d)*DS;
            #pragma unroll
            for (int k = 0; k < 8; k++) {
                double sp2 = *(const double*)(g_sp + base + 2*k);
                double sh2 = *(const double*)(g_sh + base + 2*k);
                h2[k] = ffma2(sp2, h2[k], sh2);
            }
        }
        for (int l = 0; l < CLEN; l++) {
            float x = bdt;
            #pragma unroll
            for (int r = 0; r < DTR; r++) x = fmaf(sdt[l*DTR+r], wdt[r], x);
            float dtv = (x > 20.f) ? x : log1pf(__expf(x));
            float xv  = xcp[(size_t)l*DI];
            float zv  = zgp[(size_t)l*768];
            float dtx = dtv * xv;
            float rv = __expf(-dtv);
            float rr = rv*rv;
            double dA2[8];
            dA2[0] = pack2(rv, rr);
            double rr2 = pack2(rr, rr);
            #pragma unroll
            for (int k = 1; k < 8; k++) dA2[k] = fmul2(dA2[k-1], rr2);
            double dtx2 = pack2(dtx, dtx);
            const double* B2 = (const double*)(sB + l*DS);
            const double* C2 = (const double*)(sC + l*DS);
            double a2a = pack2(xv*dsk, 0.f);
            double a2b = 0.0;
            #pragma unroll
            for (int k = 0; k < 8; k++) {
                h2[k] = ffma2(dA2[k], h2[k], fmul2(dtx2, B2[k]));
                if (k < 4) a2a = ffma2(h2[k], C2[k], a2a);
                else       a2b = ffma2(h2[k], C2[k], a2b);
            }
            float s0,s1,s2,s3;
            unpack2(a2a, s0, s1);
            unpack2(a2b, s2, s3);
            float acc = (s0+s1) + (s2+s3);
            float sg = __fdividef(zv, 1.f + __expf(-zv));
            yp[(size_t)l*DI] = acc * sg;
        }
    } else {
        float h[DS];
        #pragma unroll
        for (int n = 0; n < DS; n++) h[n] = 0.f;
        for (int cc = 0; cc < c; cc++) {
            size_t base = (((size_t)b*NCHUNK + cc)*DI + d)*DS;
            #pragma unroll
            for (int n = 0; n < DS; n++)
                h[n] = fmaf(__ldg(g_sp + base + n), h[n], __ldg(g_sh + base + n));
        }
        for (int l = 0; l < CLEN; l++) {
            float x = bdt;
            #pragma unroll
            for (int r = 0; r < DTR; r++) x = fmaf(sdt[l*DTR+r], wdt[r], x);
            float dtv = (x > 20.f) ? x : log1pf(__expf(x));
            float xv  = xcp[(size_t)l*DI];
            float zv  = zgp[(size_t)l*768];
            float dtx = dtv * xv;
            const float* Bl = sB + l*DS;
            const float* Cl = sC + l*DS;
            float a0 = xv*dsk, a1 = 0.f, a2 = 0.f, a3 = 0.f;
            #pragma unroll
            for (int n = 0; n < DS; n += 4) {
                float d0 = __expf(dtv*Av[n+0]), d1 = __expf(dtv*Av[n+1]);
                float d2 = __expf(dtv*Av[n+2]), d3 = __expf(dtv*Av[n+3]);
                h[n+0] = fmaf(d0, h[n+0], dtx*Bl[n+0]);
                h[n+1] = fmaf(d1, h[n+1], dtx*Bl[n+1]);
                h[n+2] = fmaf(d2, h[n+2], dtx*Bl[n+2]);
                h[n+3] = fmaf(d3, h[n+3], dtx*Bl[n+3]);
                a0 = fmaf(h[n+0], Cl[n+0], a0);
                a1 = fmaf(h[n+1], Cl[n+1], a1);
                a2 = fmaf(h[n+2], Cl[n+2], a2);
                a3 = fmaf(h[n+3], Cl[n+3], a3);
            }
            float acc = (a0+a1) + (a2+a3);
            float sg = __fdividef(zv, 1.f + __expf(-zv));
            yp[(size_t)l*DI] = acc * sg;
        }
    }
}

// ---------------- host ----------------
extern "C" void kernel_launch(void* const* d_in, const int* in_sizes, int n_in,
                              void* d_out, int out_size)
{
    const float* x_img   = (const float*)d_in[0];
    const float* z_img   = (const float*)d_in[1];
    const float* patch_w = (const float*)d_in[2];
    const float* patch_b = (const float*)d_in[3];
    const float* pos_x   = (const float*)d_in[4];
    const float* pos_z   = (const float*)d_in[5];
    const float* ln_w    = (const float*)d_in[6];
    const float* ln_b    = (const float*)d_in[7];
    const float* in_w    = (const float*)d_in[8];
    const float* conv_w  = (const float*)d_in[9];
    const float* conv_b  = (const float*)d_in[10];
    const float* xproj_w = (const float*)d_in[11];
    const float* dt_w    = (const float*)d_in[12];
    const float* dt_b    = (const float*)d_in[13];
    const float* A_log   = (const float*)d_in[14];
    const float* D_skip  = (const float*)d_in[15];
    const float* out_w   = (const float*)d_in[16];
    const float* fnorm_w = (const float*)d_in[17];
    const float* fnorm_b = (const float*)d_in[18];

    float *p_hn, *p_xz, *p_xc, *p_dbl, *p_y, *p_hid;
    cudaGetSymbolAddress((void**)&p_hn,  g_hn);
    cudaGetSymbolAddress((void**)&p_xz,  g_xz);
    cudaGetSymbolAddress((void**)&p_xc,  g_xc);
    cudaGetSymbolAddress((void**)&p_dbl, g_dbl);
    cudaGetSymbolAddress((void**)&p_y,   g_y);
    cudaGetSymbolAddress((void**)&p_hid, g_hid);

    patch_kernel<<<dim3(40,16), 192>>>(x_img, z_img, patch_w, patch_b, pos_x, pos_z);

    for (int ly = 0; ly < NLAYER; ly++) {
        addnorm_kernel<<<1280,128>>>(ln_w + (size_t)ly*DM, ln_b + (size_t)ly*DM,
                                     nullptr, ly == 0 ? 0 : 1);
        gemm128_kernel<<<dim3(40,6),256>>>(p_hn, in_w + (size_t)ly*768*DM, p_xz,
                                           DM, 2*DI);
        conv_silu_kernel<<<1920,256>>>(conv_w + (size_t)ly*DI*4, conv_b + (size_t)ly*DI);
        gemm_kernel<<<dim3(80,1),256>>>(p_xc, xproj_w + (size_t)ly*44*DI, p_dbl,
                                        NROWS, 44, DI, 64);
        scanA_kernel<<<dim3(NCHUNK,6,BATCH),64>>>(A_log + (size_t)ly*DI*DS,
                                                  dt_w + (size_t)ly*DI*DTR,
                                                  dt_b + (size_t)ly*DI);
        scanC_kernel<<<dim3(NCHUNK,6,BATCH),64>>>(A_log + (size_t)ly*DI*DS,
                                                  D_skip + (size_t)ly*DI,
                                                  dt_w + (size_t)ly*DI*DTR,
                                                  dt_b + (size_t)ly*DI);
        gemm_n64_kernel<<<dim3(40,3),256>>>(p_y, out_w + (size_t)ly*DM*DI, p_hid,
                                            DI, DM);
    }
    addnorm_kernel<<<1280,128>>>(fnorm_w, fnorm_b, (float*)d_out, 2);
}

// round 17
// speedup vs baseline: 1.1709x; 1.0420x over previous
#include <cuda_runtime.h>

#define BATCH 16
#define SEQ   320
#define DM    192
#define DI    384
#define DS    16
#define DTR   12
#define NLAYER 24
#define NROWS (BATCH*SEQ)   // 5120
#define NCHUNK 8
#define CLEN  (SEQ/NCHUNK)  // 40

// ---------------- f32x2 packed helpers (Blackwell FFMA2 path) ----------------
__device__ __forceinline__ double ffma2(double a, double b, double c) {
    double d; asm("fma.rn.f32x2 %0,%1,%2,%3;" : "=d"(d) : "d"(a), "d"(b), "d"(c)); return d;
}
__device__ __forceinline__ double fmul2(double a, double b) {
    double d; asm("mul.rn.f32x2 %0,%1,%2;" : "=d"(d) : "d"(a), "d"(b)); return d;
}
__device__ __forceinline__ double pack2(float lo, float hi) {
    double d; asm("mov.b64 %0,{%1,%2};" : "=d"(d) : "f"(lo), "f"(hi)); return d;
}
__device__ __forceinline__ void unpack2(double d, float& lo, float& hi) {
    asm("mov.b64 {%0,%1},%2;" : "=f"(lo), "=f"(hi) : "d"(d));
}

// ---------------- scratch (no allocations allowed) ----------------
__device__ __align__(128) float g_res[NROWS*DM];
__device__ __align__(128) float g_hid[NROWS*DM];
__device__ __align__(128) float g_hn [NROWS*DM];
__device__ __align__(128) float g_xz [NROWS*2*DI];
__device__ __align__(128) float g_xc [NROWS*DI];
__device__ __align__(128) float g_dbl[NROWS*64];
__device__ __align__(128) float g_y  [NROWS*DI];
__device__ __align__(128) float g_sp [BATCH*NCHUNK*DI*DS];
__device__ __align__(128) float g_sh [BATCH*NCHUNK*DI*DS];

// ---------------- patch embed (+pos) -> g_hid ----------------
__global__ __launch_bounds__(192) void patch_kernel(
    const float* __restrict__ x_img, const float* __restrict__ z_img,
    const float* __restrict__ pw, const float* __restrict__ pb,
    const float* __restrict__ pos_x, const float* __restrict__ pos_z)
{
    __shared__ float sp[8*768];
    __shared__ float ws[192*17];
    int b   = blockIdx.y;
    int l0  = blockIdx.x * 8;
    int tid = threadIdx.x;
    bool is_z = (l0 < 64);
    const float* img = is_z ? z_img : x_img;
    int imgW = is_z ? 128 : 256;
    int gw   = is_z ? 8 : 16;
    const float* base = img + (size_t)b*3*imgW*imgW;

    for (int tok = 0; tok < 8; tok++) {
        int t  = is_z ? (l0+tok) : (l0+tok-64);
        int ph = t / gw, pwc = t % gw;
        const float* pbase = base + (size_t)(ph*16)*imgW + pwc*16;
        #pragma unroll
        for (int q = 0; q < 4; q++) {
            int idx = tid + q*192;
            int c = idx >> 8, r = idx & 255;
            sp[tok*768 + idx] = pbase[(size_t)c*imgW*imgW + (r>>4)*imgW + (r&15)];
        }
    }
    float acc[8];
    #pragma unroll
    for (int t = 0; t < 8; t++) acc[t] = 0.f;

    for (int k0 = 0; k0 < 768; k0 += 16) {
        __syncthreads();
        #pragma unroll
        for (int q = 0; q < 16; q++) {
            int idx = tid + q*192;
            int o = idx >> 4, kk = idx & 15;
            ws[o*17 + kk] = pw[(size_t)o*768 + k0 + kk];
        }
        __syncthreads();
        #pragma unroll
        for (int kk = 0; kk < 16; kk++) {
            float wv = ws[tid*17 + kk];
            #pragma unroll
            for (int t = 0; t < 8; t++)
                acc[t] = fmaf(wv, sp[t*768 + k0 + kk], acc[t]);
        }
    }
    float bias = pb[tid];
    for (int tok = 0; tok < 8; tok++) {
        int l = l0 + tok;
        float pos = is_z ? pos_z[(size_t)l*DM + tid] : pos_x[(size_t)(l-64)*DM + tid];
        g_hid[((size_t)b*SEQ + l)*DM + tid] = acc[tok] + bias + pos;
    }
}

// ---------------- fused residual add + layernorm ----------------
__global__ __launch_bounds__(128) void addnorm_kernel(
    const float* __restrict__ w, const float* __restrict__ bb,
    float* __restrict__ extout, int mode)
{
    int row  = blockIdx.x*4 + (threadIdx.x >> 5);
    int lane = threadIdx.x & 31;
    float*       res = g_res + (size_t)row*DM;
    const float* hid = g_hid + (size_t)row*DM;
    float v[6];
    #pragma unroll
    for (int q = 0; q < 6; q++) {
        int i = lane + q*32;
        float r = (mode == 0) ? hid[i] : (res[i] + hid[i]);
        res[i] = r;
        v[q] = r;
    }
    float s = v[0]+v[1]+v[2]+v[3]+v[4]+v[5];
    #pragma unroll
    for (int off = 16; off; off >>= 1) s += __shfl_xor_sync(0xffffffffu, s, off);
    float mu = s * (1.f/192.f);
    float var = 0.f;
    #pragma unroll
    for (int q = 0; q < 6; q++) { float dd = v[q]-mu; var = fmaf(dd, dd, var); }
    #pragma unroll
    for (int off = 16; off; off >>= 1) var += __shfl_xor_sync(0xffffffffu, var, off);
    float inv = rsqrtf(var*(1.f/192.f) + 1e-5f);
    float* outp = (mode == 2) ? (extout + (size_t)row*DM) : (g_hn + (size_t)row*DM);
    #pragma unroll
    for (int q = 0; q < 6; q++) {
        int i = lane + q*32;
        outp[i] = (v[q]-mu)*inv*w[i] + bb[i];
    }
}

// ================ big GEMM: 128x128 tile, 8x8 microtile, f32x2, double-buffered ================
__global__ __launch_bounds__(256) void gemm128_kernel(
    const float* __restrict__ A, const float* __restrict__ W,
    float* __restrict__ C, int K, int N)
{
    __shared__ __align__(16) float As[2][16][136];
    __shared__ __align__(16) float Ws[2][16][136];
    int m0 = blockIdx.x * 128;
    int n0 = blockIdx.y * 128;
    int tid = threadIdx.x;
    int lr  = tid >> 2;
    int lc  = (tid & 3) << 2;
    int tx  = tid & 15;
    int ty  = tid >> 4;
    const float* Ap0 = A + (size_t)(m0 + lr)*K + lc;
    const float* Ap1 = A + (size_t)(m0 + 64 + lr)*K + lc;
    const float* Wp0 = W + (size_t)(n0 + lr)*K + lc;
    const float* Wp1 = W + (size_t)(n0 + 64 + lr)*K + lc;

    float4 a0 = *(const float4*)Ap0;
    float4 a1 = *(const float4*)Ap1;
    float4 w0 = *(const float4*)Wp0;
    float4 w1 = *(const float4*)Wp1;

    double acc2[8][4];
    #pragma unroll
    for (int i = 0; i < 8; i++)
        #pragma unroll
        for (int j = 0; j < 4; j++) acc2[i][j] = 0.0;

    int ktiles = K >> 4;
    int buf = 0;
    As[0][lc+0][lr]=a0.x; As[0][lc+1][lr]=a0.y; As[0][lc+2][lr]=a0.z; As[0][lc+3][lr]=a0.w;
    As[0][lc+0][64+lr]=a1.x; As[0][lc+1][64+lr]=a1.y; As[0][lc+2][64+lr]=a1.z; As[0][lc+3][64+lr]=a1.w;
    Ws[0][lc+0][lr]=w0.x; Ws[0][lc+1][lr]=w0.y; Ws[0][lc+2][lr]=w0.z; Ws[0][lc+3][lr]=w0.w;
    Ws[0][lc+0][64+lr]=w1.x; Ws[0][lc+1][64+lr]=w1.y; Ws[0][lc+2][64+lr]=w1.z; Ws[0][lc+3][64+lr]=w1.w;
    __syncthreads();

    for (int t = 1; t < ktiles; t++) {
        a0 = *(const float4*)(Ap0 + t*16);
        a1 = *(const float4*)(Ap1 + t*16);
        w0 = *(const float4*)(Wp0 + t*16);
        w1 = *(const float4*)(Wp1 + t*16);
        #pragma unroll
        for (int k = 0; k < 16; k++) {
            float4 aA = *(const float4*)&As[buf][k][ty<<3];
            float4 aB = *(const float4*)&As[buf][k][(ty<<3)+4];
            double2 bd0 = *(const double2*)&Ws[buf][k][tx<<3];
            double2 bd1 = *(const double2*)&Ws[buf][k][(tx<<3)+4];
            double am2[8];
            am2[0]=pack2(aA.x,aA.x); am2[1]=pack2(aA.y,aA.y);
            am2[2]=pack2(aA.z,aA.z); am2[3]=pack2(aA.w,aA.w);
            am2[4]=pack2(aB.x,aB.x); am2[5]=pack2(aB.y,aB.y);
            am2[6]=pack2(aB.z,aB.z); am2[7]=pack2(aB.w,aB.w);
            #pragma unroll
            for (int i = 0; i < 8; i++) {
                acc2[i][0] = ffma2(am2[i], bd0.x, acc2[i][0]);
                acc2[i][1] = ffma2(am2[i], bd0.y, acc2[i][1]);
                acc2[i][2] = ffma2(am2[i], bd1.x, acc2[i][2]);
                acc2[i][3] = ffma2(am2[i], bd1.y, acc2[i][3]);
            }
        }
        int ob = buf ^ 1;
        As[ob][lc+0][lr]=a0.x; As[ob][lc+1][lr]=a0.y; As[ob][lc+2][lr]=a0.z; As[ob][lc+3][lr]=a0.w;
        As[ob][lc+0][64+lr]=a1.x; As[ob][lc+1][64+lr]=a1.y; As[ob][lc+2][64+lr]=a1.z; As[ob][lc+3][64+lr]=a1.w;
        Ws[ob][lc+0][lr]=w0.x; Ws[ob][lc+1][lr]=w0.y; Ws[ob][lc+2][lr]=w0.z; Ws[ob][lc+3][lr]=w0.w;
        Ws[ob][lc+0][64+lr]=w1.x; Ws[ob][lc+1][64+lr]=w1.y; Ws[ob][lc+2][64+lr]=w1.z; Ws[ob][lc+3][64+lr]=w1.w;
        __syncthreads();
        buf = ob;
    }
    #pragma unroll
    for (int k = 0; k < 16; k++) {
        float4 aA = *(const float4*)&As[buf][k][ty<<3];
        float4 aB = *(const float4*)&As[buf][k][(ty<<3)+4];
        double2 bd0 = *(const double2*)&Ws[buf][k][tx<<3];
        double2 bd1 = *(const double2*)&Ws[buf][k][(tx<<3)+4];
        double am2[8];
        am2[0]=pack2(aA.x,aA.x); am2[1]=pack2(aA.y,aA.y);
        am2[2]=pack2(aA.z,aA.z); am2[3]=pack2(aA.w,aA.w);
        am2[4]=pack2(aB.x,aB.x); am2[5]=pack2(aB.y,aB.y);
        am2[6]=pack2(aB.z,aB.z); am2[7]=pack2(aB.w,aB.w);
        #pragma unroll
        for (int i = 0; i < 8; i++) {
            acc2[i][0] = ffma2(am2[i], bd0.x, acc2[i][0]);
            acc2[i][1] = ffma2(am2[i], bd0.y, acc2[i][1]);
            acc2[i][2] = ffma2(am2[i], bd1.x, acc2[i][2]);
            acc2[i][3] = ffma2(am2[i], bd1.y, acc2[i][3]);
        }
    }
    #pragma unroll
    for (int i = 0; i < 8; i++) {
        float* crow = C + (size_t)(m0 + (ty<<3) + i)*N + n0 + (tx<<3);
        *(double2*)crow       = make_double2(acc2[i][0], acc2[i][1]);
        *(double2*)(crow + 4) = make_double2(acc2[i][2], acc2[i][3]);
    }
}

// ================ out_proj GEMM: 128x64 tile, 8x4 microtile, f32x2, double-buffered ================
__global__ __launch_bounds__(256) void gemm_n64_kernel(
    const float* __restrict__ A, const float* __restrict__ W,
    float* __restrict__ C, int K, int N)
{
    __shared__ __align__(16) float As[2][16][136];
    __shared__ __align__(16) float Ws[2][16][72];
    int m0 = blockIdx.x * 128;
    int n0 = blockIdx.y * 64;
    int tid = threadIdx.x;
    int lr  = tid >> 2;
    int lc  = (tid & 3) << 2;
    int tx  = tid & 15;
    int ty  = tid >> 4;
    const float* Ap0 = A + (size_t)(m0 + lr)*K + lc;
    const float* Ap1 = A + (size_t)(m0 + 64 + lr)*K + lc;
    const float* Wp  = W + (size_t)(n0 + lr)*K + lc;

    float4 a0 = *(const float4*)Ap0;
    float4 a1 = *(const float4*)Ap1;
    float4 w0 = *(const float4*)Wp;

    double acc2[8][2];
    #pragma unroll
    for (int i = 0; i < 8; i++) { acc2[i][0] = 0.0; acc2[i][1] = 0.0; }

    int ktiles = K >> 4;
    int buf = 0;
    As[0][lc+0][lr]=a0.x; As[0][lc+1][lr]=a0.y; As[0][lc+2][lr]=a0.z; As[0][lc+3][lr]=a0.w;
    As[0][lc+0][64+lr]=a1.x; As[0][lc+1][64+lr]=a1.y; As[0][lc+2][64+lr]=a1.z; As[0][lc+3][64+lr]=a1.w;
    Ws[0][lc+0][lr]=w0.x; Ws[0][lc+1][lr]=w0.y; Ws[0][lc+2][lr]=w0.z; Ws[0][lc+3][lr]=w0.w;
    __syncthreads();

    for (int t = 1; t < ktiles; t++) {
        a0 = *(const float4*)(Ap0 + t*16);
        a1 = *(const float4*)(Ap1 + t*16);
        w0 = *(const float4*)(Wp  + t*16);
        #pragma unroll
        for (int k = 0; k < 16; k++) {
            float4 aA = *(const float4*)&As[buf][k][ty<<3];
            float4 aB = *(const float4*)&As[buf][k][(ty<<3)+4];
            double2 bd = *(const double2*)&Ws[buf][k][tx<<2];
            double am2[8];
            am2[0]=pack2(aA.x,aA.x); am2[1]=pack2(aA.y,aA.y);
            am2[2]=pack2(aA.z,aA.z); am2[3]=pack2(aA.w,aA.w);
            am2[4]=pack2(aB.x,aB.x); am2[5]=pack2(aB.y,aB.y);
            am2[6]=pack2(aB.z,aB.z); am2[7]=pack2(aB.w,aB.w);
            #pragma unroll
            for (int i = 0; i < 8; i++) {
                acc2[i][0] = ffma2(am2[i], bd.x, acc2[i][0]);
                acc2[i][1] = ffma2(am2[i], bd.y, acc2[i][1]);
            }
        }
        int ob = buf ^ 1;
        As[ob][lc+0][lr]=a0.x; As[ob][lc+1][lr]=a0.y; As[ob][lc+2][lr]=a0.z; As[ob][lc+3][lr]=a0.w;
        As[ob][lc+0][64+lr]=a1.x; As[ob][lc+1][64+lr]=a1.y; As[ob][lc+2][64+lr]=a1.z; As[ob][lc+3][64+lr]=a1.w;
        Ws[ob][lc+0][lr]=w0.x; Ws[ob][lc+1][lr]=w0.y; Ws[ob][lc+2][lr]=w0.z; Ws[ob][lc+3][lr]=w0.w;
        __syncthreads();
        buf = ob;
    }
    #pragma unroll
    for (int k = 0; k < 16; k++) {
        float4 aA = *(const float4*)&As[buf][k][ty<<3];
        float4 aB = *(const float4*)&As[buf][k][(ty<<3)+4];
        double2 bd = *(const double2*)&Ws[buf][k][tx<<2];
        double am2[8];
        am2[0]=pack2(aA.x,aA.x); am2[1]=pack2(aA.y,aA.y);
        am2[2]=pack2(aA.z,aA.z); am2[3]=pack2(aA.w,aA.w);
        am2[4]=pack2(aB.x,aB.x); am2[5]=pack2(aB.y,aB.y);
        am2[6]=pack2(aB.z,aB.z); am2[7]=pack2(aB.w,aB.w);
        #pragma unroll
        for (int i = 0; i < 8; i++) {
            acc2[i][0] = ffma2(am2[i], bd.x, acc2[i][0]);
            acc2[i][1] = ffma2(am2[i], bd.y, acc2[i][1]);
        }
    }
    #pragma unroll
    for (int i = 0; i < 8; i++) {
        float* crow = C + (size_t)(m0 + (ty<<3) + i)*N + n0 + (tx<<2);
        *(double2*)crow = make_double2(acc2[i][0], acc2[i][1]);
    }
}

// ---------------- x_proj GEMM: 64x64 tile, f32x2, double-buffered ----------------
__global__ __launch_bounds__(256) void gemm_kernel(
    const float* __restrict__ A, const float* __restrict__ W,
    float* __restrict__ C, int M, int N, int K, int ldc)
{
    __shared__ __align__(16) float As[2][16][72];
    __shared__ __align__(16) float Ws[2][16][72];
    int m0 = blockIdx.x * 64;
    int n0 = blockIdx.y * 64;
    int tid = threadIdx.x;
    int tx = tid & 15, ty = tid >> 4;
    int lr = tid >> 2;
    int lk = (tid & 3) << 2;
    const float* Aptr = A + (size_t)(m0+lr)*K + lk;
    bool wvalid = (n0 + lr < N);
    const float* Wptr = W + (size_t)(wvalid ? (n0+lr) : 0)*K + lk;

    float4 av = *(const float4*)Aptr;
    float4 wv = wvalid ? *(const float4*)Wptr : make_float4(0.f,0.f,0.f,0.f);
    As[0][lk+0][lr]=av.x; As[0][lk+1][lr]=av.y; As[0][lk+2][lr]=av.z; As[0][lk+3][lr]=av.w;
    Ws[0][lk+0][lr]=wv.x; Ws[0][lk+1][lr]=wv.y; Ws[0][lk+2][lr]=wv.z; Ws[0][lk+3][lr]=wv.w;
    __syncthreads();

    double acc2[4][2];
    #pragma unroll
    for (int i = 0; i < 4; i++) { acc2[i][0] = 0.0; acc2[i][1] = 0.0; }

    int ktiles = K >> 4;
    int buf = 0;
    for (int t = 1; t < ktiles; t++) {
        float4 av2 = *(const float4*)(Aptr + t*16);
        float4 wv2 = wvalid ? *(const float4*)(Wptr + t*16) : make_float4(0.f,0.f,0.f,0.f);
        #pragma unroll
        for (int k = 0; k < 16; k++) {
            float4 a4 = *(const float4*)&As[buf][k][ty<<2];
            double2 bd = *(const double2*)&Ws[buf][k][tx<<2];
            double am2[4];
            am2[0]=pack2(a4.x,a4.x); am2[1]=pack2(a4.y,a4.y);
            am2[2]=pack2(a4.z,a4.z); am2[3]=pack2(a4.w,a4.w);
            #pragma unroll
            for (int i = 0; i < 4; i++) {
                acc2[i][0] = ffma2(am2[i], bd.x, acc2[i][0]);
                acc2[i][1] = ffma2(am2[i], bd.y, acc2[i][1]);
            }
        }
        int ob = buf ^ 1;
        As[ob][lk+0][lr]=av2.x; As[ob][lk+1][lr]=av2.y; As[ob][lk+2][lr]=av2.z; As[ob][lk+3][lr]=av2.w;
        Ws[ob][lk+0][lr]=wv2.x; Ws[ob][lk+1][lr]=wv2.y; Ws[ob][lk+2][lr]=wv2.z; Ws[ob][lk+3][lr]=wv2.w;
        __syncthreads();
        buf = ob;
    }
    #pragma unroll
    for (int k = 0; k < 16; k++) {
        float4 a4 = *(const float4*)&As[buf][k][ty<<2];
        double2 bd = *(const double2*)&Ws[buf][k][tx<<2];
        double am2[4];
        am2[0]=pack2(a4.x,a4.x); am2[1]=pack2(a4.y,a4.y);
        am2[2]=pack2(a4.z,a4.z); am2[3]=pack2(a4.w,a4.w);
        #pragma unroll
        for (int i = 0; i < 4; i++) {
            acc2[i][0] = ffma2(am2[i], bd.x, acc2[i][0]);
            acc2[i][1] = ffma2(am2[i], bd.y, acc2[i][1]);
        }
    }
    #pragma unroll
    for (int i = 0; i < 4; i++) {
        int row = m0 + (ty<<2) + i;
        int c0  = n0 + (tx<<2);
        float f0,f1,f2,f3;
        unpack2(acc2[i][0], f0, f1);
        unpack2(acc2[i][1], f2, f3);
        float* crow = C + (size_t)row*ldc + c0;
        if (c0+0 < N) crow[0] = f0;
        if (c0+1 < N) crow[1] = f1;
        if (c0+2 < N) crow[2] = f2;
        if (c0+3 < N) crow[3] = f3;
    }
}

// ---------------- causal depthwise conv (k=4) + silu, 4 timesteps/thread ----------------
__global__ __launch_bounds__(256) void conv_silu_kernel(
    const float* __restrict__ cw, const float* __restrict__ cb)
{
    int id = blockIdx.x*256 + threadIdx.x;
    int d  = id % DI;
    int t  = id / DI;
    int lq = t % (SEQ/4);
    int b  = t / (SEQ/4);
    int l0 = lq*4;
    const float* xp = g_xz + ((size_t)b*SEQ + l0)*768 + d;
    float x0 = xp[0], x1 = xp[768], x2 = xp[2*768], x3 = xp[3*768];
    float xm1 = 0.f, xm2 = 0.f, xm3 = 0.f;
    if (l0) { xm1 = xp[-768]; xm2 = xp[-2*768]; xm3 = xp[-3*768]; }
    float w0 = __ldg(cw + d*4 + 0), w1 = __ldg(cw + d*4 + 1);
    float w2 = __ldg(cw + d*4 + 2), w3 = __ldg(cw + d*4 + 3);
    float bv = __ldg(cb + d);
    float y0 = fmaf(w3,x0, fmaf(w2,xm1, fmaf(w1,xm2, fmaf(w0,xm3, bv))));
    float y1 = fmaf(w3,x1, fmaf(w2,x0,  fmaf(w1,xm1, fmaf(w0,xm2, bv))));
    float y2 = fmaf(w3,x2, fmaf(w2,x1,  fmaf(w1,x0,  fmaf(w0,xm1, bv))));
    float y3 = fmaf(w3,x3, fmaf(w2,x2,  fmaf(w1,x1,  fmaf(w0,x0,  bv))));
    float* yo = g_xc + ((size_t)b*SEQ + l0)*DI + d;
    yo[0]    = __fdividef(y0, 1.f + __expf(-y0));
    yo[DI]   = __fdividef(y1, 1.f + __expf(-y1));
    yo[2*DI] = __fdividef(y2, 1.f + __expf(-y2));
    yo[3*DI] = __fdividef(y3, 1.f + __expf(-y3));
}

// ---- dt dot-product: 4-way tree + fast softplus (shared by both scans) ----
__device__ __forceinline__ float dt_eval(const float* __restrict__ sdtl,
                                         const float* __restrict__ wdt, float bdt)
{
    float x0 = bdt, x1 = 0.f, x2 = 0.f, x3 = 0.f;
    x0 = fmaf(sdtl[0], wdt[0], x0);  x1 = fmaf(sdtl[1],  wdt[1],  x1);
    x2 = fmaf(sdtl[2], wdt[2], x2);  x3 = fmaf(sdtl[3],  wdt[3],  x3);
    x0 = fmaf(sdtl[4], wdt[4], x0);  x1 = fmaf(sdtl[5],  wdt[5],  x1);
    x2 = fmaf(sdtl[6], wdt[6], x2);  x3 = fmaf(sdtl[7],  wdt[7],  x3);
    x0 = fmaf(sdtl[8], wdt[8], x0);  x1 = fmaf(sdtl[9],  wdt[9],  x1);
    x2 = fmaf(sdtl[10], wdt[10], x2); x3 = fmaf(sdtl[11], wdt[11], x3);
    float x = (x0+x1) + (x2+x3);
    return (x > 20.f) ? x : __logf(1.f + __expf(x));
}

// ============ chunked selective scan (NCHUNK=8, f32x2, fused dt_proj+softplus) ============
// scanA launched with grid.x = NCHUNK-1 (last chunk's state is never consumed).
__global__ __launch_bounds__(64) void scanA_kernel(
    const float* __restrict__ A_log,
    const float* __restrict__ dtw, const float* __restrict__ dtb)
{
    __shared__ __align__(16) float sB[CLEN*DS];
    __shared__ __align__(16) float sdt[CLEN*DTR];
    int c   = blockIdx.x;
    int d   = blockIdx.y*64 + threadIdx.x;
    int b   = blockIdx.z;
    int l0  = c*CLEN;
    for (int idx = threadIdx.x; idx < CLEN*DS; idx += 64) {
        int l = idx >> 4, n = idx & 15;
        sB[idx] = g_dbl[((size_t)b*SEQ + l0 + l)*64 + 12 + n];
    }
    for (int idx = threadIdx.x; idx < CLEN*DTR; idx += 64) {
        int l = idx / DTR, r = idx - l*DTR;
        sdt[idx] = g_dbl[((size_t)b*SEQ + l0 + l)*64 + r];
    }
    __syncthreads();
    float Av[DS];
    bool fast = true;
    #pragma unroll
    for (int n = 0; n < DS; n++) {
        Av[n] = -__expf(A_log[(size_t)d*DS + n]);
        fast = fast && (fabsf(Av[n] + (float)(n+1)) < 1e-5f*(float)(n+1));
    }
    float wdt[DTR];
    #pragma unroll
    for (int r = 0; r < DTR; r++) wdt[r] = __ldg(dtw + (size_t)d*DTR + r);
    float bdt = __ldg(dtb + d);

    const float* xcp = g_xc + ((size_t)b*SEQ + l0)*DI + d;
    size_t base = (((size_t)b*NCHUNK + c)*DI + d)*DS;

    if (fast) {
        double P2[8], h2[8];
        #pragma unroll
        for (int k = 0; k < 8; k++) { P2[k] = pack2(1.f,1.f); h2[k] = 0.0; }
        for (int l = 0; l < CLEN; l++) {
            float dtv = dt_eval(sdt + l*DTR, wdt, bdt);
            float xv  = xcp[(size_t)l*DI];
            float dtx = dtv * xv;
            float rv = __expf(-dtv);
            float rr = rv*rv;
            double dA2[8];
            dA2[0] = pack2(rv, rr);
            double rr2 = pack2(rr, rr);
            #pragma unroll
            for (int k = 1; k < 8; k++) dA2[k] = fmul2(dA2[k-1], rr2);
            double dtx2 = pack2(dtx, dtx);
            const double* B2 = (const double*)(sB + l*DS);
            #pragma unroll
            for (int k = 0; k < 8; k++) {
                P2[k] = fmul2(P2[k], dA2[k]);
                h2[k] = ffma2(dA2[k], h2[k], fmul2(dtx2, B2[k]));
            }
        }
        #pragma unroll
        for (int k = 0; k < 8; k++) {
            *(double*)(g_sp + base + 2*k) = P2[k];
            *(double*)(g_sh + base + 2*k) = h2[k];
        }
    } else {
        float P[DS], H[DS];
        #pragma unroll
        for (int n = 0; n < DS; n++) { P[n] = 1.f; H[n] = 0.f; }
        for (int l = 0; l < CLEN; l++) {
            float dtv = dt_eval(sdt + l*DTR, wdt, bdt);
            float xv  = xcp[(size_t)l*DI];
            float dtx = dtv * xv;
            const float* Bl = sB + l*DS;
            #pragma unroll
            for (int n = 0; n < DS; n++) {
                float dA = __expf(dtv * Av[n]);
                P[n] *= dA;
                H[n]  = fmaf(dA, H[n], dtx * Bl[n]);
            }
        }
        #pragma unroll
        for (int n = 0; n < DS; n++) { g_sp[base+n] = P[n]; g_sh[base+n] = H[n]; }
    }
}

__global__ __launch_bounds__(64) void scanC_kernel(
    const float* __restrict__ A_log, const float* __restrict__ Dskip,
    const float* __restrict__ dtw, const float* __restrict__ dtb)
{
    __shared__ __align__(16) float sB[CLEN*DS];
    __shared__ __align__(16) float sC[CLEN*DS];
    __shared__ __align__(16) float sdt[CLEN*DTR];
    int c   = blockIdx.x;
    int d   = blockIdx.y*64 + threadIdx.x;
    int b   = blockIdx.z;
    int l0  = c*CLEN;
    for (int idx = threadIdx.x; idx < CLEN*DS; idx += 64) {
        int l = idx >> 4, n = idx & 15;
        const float* row = g_dbl + ((size_t)b*SEQ + l0 + l)*64;
        sB[idx] = row[12 + n];
        sC[idx] = row[28 + n];
    }
    for (int idx = threadIdx.x; idx < CLEN*DTR; idx += 64) {
        int l = idx / DTR, r = idx - l*DTR;
        sdt[idx] = g_dbl[((size_t)b*SEQ + l0 + l)*64 + r];
    }
    __syncthreads();
    float Av[DS];
    bool fast = true;
    #pragma unroll
    for (int n = 0; n < DS; n++) {
        Av[n] = -__expf(A_log[(size_t)d*DS + n]);
        fast = fast && (fabsf(Av[n] + (float)(n+1)) < 1e-5f*(float)(n+1));
    }
    float wdt[DTR];
    #pragma unroll
    for (int r = 0; r < DTR; r++) wdt[r] = __ldg(dtw + (size_t)d*DTR + r);
    float bdt = __ldg(dtb + d);
    float dsk = __ldg(Dskip + d);

    const float* xcp = g_xc + ((size_t)b*SEQ + l0)*DI + d;
    const float* zgp = g_xz + ((size_t)b*SEQ + l0)*768 + DI + d;
    float*       yp  = g_y  + ((size_t)b*SEQ + l0)*DI + d;

    if (fast) {
        double h2[8];
        #pragma unroll
        for (int k = 0; k < 8; k++) h2[k] = 0.0;
        for (int cc = 0; cc < c; cc++) {
            size_t base = (((size_t)b*NCHUNK + cc)*DI + d)*DS;
            #pragma unroll
            for (int k = 0; k < 8; k++) {
                double sp2 = *(const double*)(g_sp + base + 2*k);
                double sh2 = *(const double*)(g_sh + base + 2*k);
                h2[k] = ffma2(sp2, h2[k], sh2);
            }
        }
        for (int l = 0; l < CLEN; l++) {
            float dtv = dt_eval(sdt + l*DTR, wdt, bdt);
            float xv  = xcp[(size_t)l*DI];
            float zv  = zgp[(size_t)l*768];
            float dtx = dtv * xv;
            float rv = __expf(-dtv);
            float rr = rv*rv;
            double dA2[8];
            dA2[0] = pack2(rv, rr);
            double rr2 = pack2(rr, rr);
            #pragma unroll
            for (int k = 1; k < 8; k++) dA2[k] = fmul2(dA2[k-1], rr2);
            double dtx2 = pack2(dtx, dtx);
            const double* B2 = (const double*)(sB + l*DS);
            const double* C2 = (const double*)(sC + l*DS);
            double a2a = pack2(xv*dsk, 0.f);
            double a2b = 0.0;
            #pragma unroll
            for (int k = 0; k < 8; k++) {
                h2[k] = ffma2(dA2[k], h2[k], fmul2(dtx2, B2[k]));
                if (k < 4) a2a = ffma2(h2[k], C2[k], a2a);
                else       a2b = ffma2(h2[k], C2[k], a2b);
            }
            float s0,s1,s2,s3;
            unpack2(a2a, s0, s1);
            unpack2(a2b, s2, s3);
            float acc = (s0+s1) + (s2+s3);
            float sg = __fdividef(zv, 1.f + __expf(-zv));
            yp[(size_t)l*DI] = acc * sg;
        }
    } else {
        float h[DS];
        #pragma unroll
        for (int n = 0; n < DS; n++) h[n] = 0.f;
        for (int cc = 0; cc < c; cc++) {
            size_t base = (((size_t)b*NCHUNK + cc)*DI + d)*DS;
            #pragma unroll
            for (int n = 0; n < DS; n++)
                h[n] = fmaf(__ldg(g_sp + base + n), h[n], __ldg(g_sh + base + n));
        }
        for (int l = 0; l < CLEN; l++) {
            float dtv = dt_eval(sdt + l*DTR, wdt, bdt);
            float xv  = xcp[(size_t)l*DI];
            float zv  = zgp[(size_t)l*768];
            float dtx = dtv * xv;
            const float* Bl = sB + l*DS;
            const float* Cl = sC + l*DS;
            float a0 = xv*dsk, a1 = 0.f, a2 = 0.f, a3 = 0.f;
            #pragma unroll
            for (int n = 0; n < DS; n += 4) {
                float d0 = __expf(dtv*Av[n+0]), d1 = __expf(dtv*Av[n+1]);
                float d2 = __expf(dtv*Av[n+2]), d3 = __expf(dtv*Av[n+3]);
                h[n+0] = fmaf(d0, h[n+0], dtx*Bl[n+0]);
                h[n+1] = fmaf(d1, h[n+1], dtx*Bl[n+1]);
                h[n+2] = fmaf(d2, h[n+2], dtx*Bl[n+2]);
                h[n+3] = fmaf(d3, h[n+3], dtx*Bl[n+3]);
                a0 = fmaf(h[n+0], Cl[n+0], a0);
                a1 = fmaf(h[n+1], Cl[n+1], a1);
                a2 = fmaf(h[n+2], Cl[n+2], a2);
                a3 = fmaf(h[n+3], Cl[n+3], a3);
            }
            float acc = (a0+a1) + (a2+a3);
            float sg = __fdividef(zv, 1.f + __expf(-zv));
            yp[(size_t)l*DI] = acc * sg;
        }
    }
}

// ---------------- host ----------------
extern "C" void kernel_launch(void* const* d_in, const int* in_sizes, int n_in,
                              void* d_out, int out_size)
{
    const float* x_img   = (const float*)d_in[0];
    const float* z_img   = (const float*)d_in[1];
    const float* patch_w = (const float*)d_in[2];
    const float* patch_b = (const float*)d_in[3];
    const float* pos_x   = (const float*)d_in[4];
    const float* pos_z   = (const float*)d_in[5];
    const float* ln_w    = (const float*)d_in[6];
    const float* ln_b    = (const float*)d_in[7];
    const float* in_w    = (const float*)d_in[8];
    const float* conv_w  = (const float*)d_in[9];
    const float* conv_b  = (const float*)d_in[10];
    const float* xproj_w = (const float*)d_in[11];
    const float* dt_w    = (const float*)d_in[12];
    const float* dt_b    = (const float*)d_in[13];
    const float* A_log   = (const float*)d_in[14];
    const float* D_skip  = (const float*)d_in[15];
    const float* out_w   = (const float*)d_in[16];
    const float* fnorm_w = (const float*)d_in[17];
    const float* fnorm_b = (const float*)d_in[18];

    float *p_hn, *p_xz, *p_xc, *p_dbl, *p_y, *p_hid;
    cudaGetSymbolAddress((void**)&p_hn,  g_hn);
    cudaGetSymbolAddress((void**)&p_xz,  g_xz);
    cudaGetSymbolAddress((void**)&p_xc,  g_xc);
    cudaGetSymbolAddress((void**)&p_dbl, g_dbl);
    cudaGetSymbolAddress((void**)&p_y,   g_y);
    cudaGetSymbolAddress((void**)&p_hid, g_hid);

    patch_kernel<<<dim3(40,16), 192>>>(x_img, z_img, patch_w, patch_b, pos_x, pos_z);

    for (int ly = 0; ly < NLAYER; ly++) {
        addnorm_kernel<<<1280,128>>>(ln_w + (size_t)ly*DM, ln_b + (size_t)ly*DM,
                                     nullptr, ly == 0 ? 0 : 1);
        gemm128_kernel<<<dim3(40,6),256>>>(p_hn, in_w + (size_t)ly*768*DM, p_xz,
                                           DM, 2*DI);
        conv_silu_kernel<<<1920,256>>>(conv_w + (size_t)ly*DI*4, conv_b + (size_t)ly*DI);
        gemm_kernel<<<dim3(80,1),256>>>(p_xc, xproj_w + (size_t)ly*44*DI, p_dbl,
                                        NROWS, 44, DI, 64);
        scanA_kernel<<<dim3(NCHUNK-1,6,BATCH),64>>>(A_log + (size_t)ly*DI*DS,
                                                    dt_w + (size_t)ly*DI*DTR,
                                                    dt_b + (size_t)ly*DI);
        scanC_kernel<<<dim3(NCHUNK,6,BATCH),64>>>(A_log + (size_t)ly*DI*DS,
                                                  D_skip + (size_t)ly*DI,
                                                  dt_w + (size_t)ly*DI*DTR,
                                                  dt_b + (size_t)ly*DI);
        gemm_n64_kernel<<<dim3(40,3),256>>>(p_y, out_w + (size_t)ly*DM*DI, p_hid,
                                            DI, DM);
    }
    addnorm_kernel<<<1280,128>>>(fnorm_w, fnorm_b, (float*)d_out, 2);
}